// round 3
// baseline (speedup 1.0000x reference)
#include <cuda_runtime.h>

#define WS 16
#define NH 8
#define CH 96
#define DH 12          // CH / NH
#define NTOK 256       // WS*WS tokens per window
#define BATCH 8
#define IMG 256        // H = W
#define HW (IMG*IMG)   // 65536
#define NWIN 2048      // BATCH * 16 * 16
#define NPIX (BATCH*HW)        // 524288
#define TOTAL (BATCH*CH*HW)    // 50331648
#define EPS 1e-6f
#define BN_EPS 1e-5f
#define QSTR 258       // padded row stride (floats), even -> 8B-aligned packed rows
#define QSTRD 129      // row stride in 64-bit units

typedef unsigned long long ull;

// ---- packed fp32x2 helpers (SASS FFMA2 path, PTX-only) ----------------------
__device__ __forceinline__ ull ffma2(ull a, ull b, ull c) {
    ull d;
    asm("fma.rn.f32x2 %0, %1, %2, %3;" : "=l"(d) : "l"(a), "l"(b), "l"(c));
    return d;
}
__device__ __forceinline__ ull fadd2(ull a, ull b) {
    ull d;
    asm("add.rn.f32x2 %0, %1, %2;" : "=l"(d) : "l"(a), "l"(b));
    return d;
}
__device__ __forceinline__ ull pack2(float lo, float hi) {
    ull d;
    asm("mov.b64 %0, {%1, %2};" : "=l"(d) : "f"(lo), "f"(hi));
    return d;
}
__device__ __forceinline__ float2 unpack2(ull v) {
    float2 f;
    asm("mov.b64 {%0, %1}, %2;" : "=f"(f.x), "=f"(f.y) : "l"(v));
    return f;
}

// scratch (device globals: allocation-free rule)
__device__ float g_out[TOTAL];   // attention output (pre-proj)
__device__ float g_y[TOTAL];     // proj output (pre-BN)
__device__ float g_sum[CH];
__device__ float g_sq[CH];
__device__ float g_scale[CH];
__device__ float g_shift[CH];

// ---------------------------------------------------------------------------
// K0: zero BN accumulators (graph-replay safe)
// ---------------------------------------------------------------------------
__global__ void k_zero() {
    int t = threadIdx.x;
    if (t < CH) { g_sum[t] = 0.f; g_sq[t] = 0.f; }
}

// ---------------------------------------------------------------------------
// K1: per-window qkv GEMM + linear attention.  One CTA = one 16x16 window.
// smem: x_s[96][256]f | w_d[36][96] dup-packed b64 | qkv[36][258]f | reductions
// ---------------------------------------------------------------------------
__global__ void __launch_bounds__(256, 1)
k_qkv_attn(const float* __restrict__ x, const float* __restrict__ w_qkv)
{
    extern __shared__ float smem[];
    float* x_s   = smem;                            // 24576 floats
    ull*   w_d   = (ull*)(smem + CH*NTOK);          // 3456 b64 (dup pairs)
    float* qkv_s = smem + CH*NTOK + 2*36*CH;        // 36*258 floats
    ull*   qkv_d = (ull*)qkv_s;
    float* kv_s   = qkv_s + 36*QSTR;                // 144
    float* ksum_s = kv_s + 144;                     // 12
    float* vsum_s = ksum_s + 12;                    // 12

    const int tid = threadIdx.x;
    const int blk = blockIdx.x;
    const int b   = blk >> 8;
    const int wIdx = blk & 255;
    const int h0 = (wIdx >> 4) * WS;
    const int w0 = (wIdx & 15) * WS;

    const int hl = tid >> 4, wl = tid & 15;
    const int pix = (h0 + hl) * IMG + (w0 + wl);

    // stage x window: x_s[c][n]
    {
        const float* xb = x + b*CH*HW + pix;
        #pragma unroll 4
        for (int c = 0; c < CH; c++)
            x_s[c*NTOK + tid] = xb[c*HW];
    }

    // GEMM thread mapping: 64 col-groups x 4 row-groups
    const int tx = tid & 63, ty = tid >> 6;
    const int n0 = tx * 4;        // 4 consecutive tokens (= 2 packed pairs)
    const int r0 = ty * 9;        // 9 rows of the 36-row chunk

    for (int h = 0; h < NH; h++) {
        __syncthreads();   // protects x_s (h=0), w_d & qkv reuse (h>0)

        // load W chunk for this head as duplicated pairs (w,w)
        for (int i = tid; i < 36*CH; i += 256) {
            int r = i / CH, c = i - r*CH;
            int grow = (r < 12) ? (h*DH + r)
                     : (r < 24) ? (CH + h*DH + (r - 12))
                                : (2*CH + h*DH + (r - 24));
            float w = w_qkv[grow*CH + c];
            w_d[i] = pack2(w, w);
        }
        __syncthreads();

        // 36x256 = W(36x96) @ X(96x256), 9x(2x f32x2) micro-tile
        ull acc[9][2];
        #pragma unroll
        for (int i = 0; i < 9; i++) { acc[i][0] = 0ull; acc[i][1] = 0ull; }

        #pragma unroll 2
        for (int c = 0; c < CH; c++) {
            ulonglong2 a = *reinterpret_cast<const ulonglong2*>(&x_s[c*NTOK + n0]);
            #pragma unroll
            for (int i = 0; i < 9; i++) {
                ull wv = w_d[(r0+i)*CH + c];
                acc[i][0] = ffma2(wv, a.x, acc[i][0]);
                acc[i][1] = ffma2(wv, a.y, acc[i][1]);
            }
        }
        {
            const int p0 = n0 >> 1;
            #pragma unroll
            for (int i = 0; i < 9; i++) {
                qkv_d[(r0+i)*QSTRD + p0]     = acc[i][0];
                qkv_d[(r0+i)*QSTRD + p0 + 1] = acc[i][1];
            }
        }
        __syncthreads();

        // per-token l2 normalization: q kept in registers, k written back
        float qn[12];
        {
            float s = 0.f;
            #pragma unroll
            for (int m = 0; m < 12; m++) { qn[m] = qkv_s[m*QSTR + tid]; s = fmaf(qn[m], qn[m], s); }
            float r = rsqrtf(s);
            #pragma unroll
            for (int m = 0; m < 12; m++) qn[m] *= r;
        }
        {
            float kr[12]; float s = 0.f;
            #pragma unroll
            for (int m = 0; m < 12; m++) { kr[m] = qkv_s[(12+m)*QSTR + tid]; s = fmaf(kr[m], kr[m], s); }
            float r = rsqrtf(s);
            #pragma unroll
            for (int m = 0; m < 12; m++) qkv_s[(12+m)*QSTR + tid] = kr[m] * r;
        }
        __syncthreads();

        // kv[m][c] = sum_n k[m][n]*v[c][n] ; ksum[m] ; vsum[c]   (packed pairs)
        if (tid < 144) {
            int m = tid / 12, c2 = tid - (tid/12)*12;
            const ull* kr = qkv_d + (12+m)*QSTRD;
            const ull* vr = qkv_d + (24+c2)*QSTRD;
            ull s2 = 0ull;
            #pragma unroll 4
            for (int n = 0; n < NTOK/2; n++) s2 = ffma2(kr[n], vr[n], s2);
            float2 f = unpack2(s2);
            kv_s[m*12 + c2] = f.x + f.y;
        } else if (tid >= 160 && tid < 172) {
            int m = tid - 160;
            const ull* kr = qkv_d + (12+m)*QSTRD;
            ull s2 = 0ull;
            #pragma unroll 4
            for (int n = 0; n < NTOK/2; n++) s2 = fadd2(s2, kr[n]);
            float2 f = unpack2(s2);
            ksum_s[m] = f.x + f.y + EPS;
        } else if (tid >= 192 && tid < 204) {
            int c2 = tid - 192;
            const ull* vr = qkv_d + (24+c2)*QSTRD;
            ull s2 = 0ull;
            #pragma unroll 4
            for (int n = 0; n < NTOK/2; n++) s2 = fadd2(s2, vr[n]);
            float2 f = unpack2(s2);
            vsum_s[c2] = f.x + f.y;
        }
        __syncthreads();

        // epilogue: out[c][n] = (q·kv[:,c] + vsum[c]) * tailor[n]
        float denom = (float)NTOK;
        #pragma unroll
        for (int m = 0; m < 12; m++) denom = fmaf(qn[m], ksum_s[m], denom);
        float tail = 1.0f / denom;

        float* ob = g_out + (b*CH + h*DH)*HW + pix;
        #pragma unroll
        for (int c2 = 0; c2 < 12; c2++) {
            float v = vsum_s[c2];
            #pragma unroll
            for (int m = 0; m < 12; m++) v = fmaf(qn[m], kv_s[m*12 + c2], v);
            ob[c2*HW] = v * tail;
        }
    }
}

// ---------------------------------------------------------------------------
// K2: proj GEMM y = w_proj(96x96) @ out(96 x 524288) + fused BN statistics.
// Block = 512 columns (2/thread).  Accumulate adjacent OUTPUT-ROW pairs in
// f32x2 so W pairs load straight from smem; activation is broadcast-dup'd.
// ---------------------------------------------------------------------------
__global__ void __launch_bounds__(256)
k_proj(const float* __restrict__ w_proj)
{
    __shared__ float w_t[CH*CH];     // transposed: w_t[c][o]
    __shared__ float red_s[2*CH];

    const int tid = threadIdx.x;
    for (int i = tid; i < CH*CH; i += 256) {
        int o = i / CH, c = i - o*CH;
        w_t[c*CH + o] = w_proj[i];
    }
    if (tid < 2*CH) red_s[tid] = 0.f;
    __syncthreads();

    const int col0 = blockIdx.x * 512 + tid;      // second col = col0+256
    const int b = col0 >> 16;                     // / HW
    const int p = col0 & (HW - 1);
    const float* src = g_out + b*CH*HW + p;
    float*       dst = g_y   + b*CH*HW + p;

    #pragma unroll 1
    for (int chk = 0; chk < 3; chk++) {
        ull a0[16], a1[16];                       // row pairs, col0 / col1
        #pragma unroll
        for (int j = 0; j < 16; j++) { a0[j] = 0ull; a1[j] = 0ull; }

        #pragma unroll 2
        for (int c = 0; c < CH; c++) {
            float v0 = src[c*HW];
            float v1 = src[c*HW + 256];
            ull vp0 = pack2(v0, v0);
            ull vp1 = pack2(v1, v1);
            const ulonglong2* wt = reinterpret_cast<const ulonglong2*>(&w_t[c*CH + chk*32]);
            #pragma unroll
            for (int q = 0; q < 8; q++) {
                ulonglong2 w2 = wt[q];
                a0[2*q]   = ffma2(w2.x, vp0, a0[2*q]);
                a1[2*q]   = ffma2(w2.x, vp1, a1[2*q]);
                a0[2*q+1] = ffma2(w2.y, vp0, a0[2*q+1]);
                a1[2*q+1] = ffma2(w2.y, vp1, a1[2*q+1]);
            }
        }
        #pragma unroll
        for (int j = 0; j < 16; j++) {
            float2 f0 = unpack2(a0[j]);   // rows (2j, 2j+1), column 0
            float2 f1 = unpack2(a1[j]);   // rows (2j, 2j+1), column 1
            int oc0 = chk*32 + 2*j;
            dst[oc0*HW]             = f0.x;
            dst[oc0*HW + 256]       = f1.x;
            dst[(oc0+1)*HW]         = f0.y;
            dst[(oc0+1)*HW + 256]   = f1.y;

            float s0 = f0.x + f1.x, q0 = fmaf(f0.x, f0.x, f1.x*f1.x);
            float s1 = f0.y + f1.y, q1 = fmaf(f0.y, f0.y, f1.y*f1.y);
            #pragma unroll
            for (int d = 16; d > 0; d >>= 1) {
                s0 += __shfl_xor_sync(0xffffffffu, s0, d);
                q0 += __shfl_xor_sync(0xffffffffu, q0, d);
                s1 += __shfl_xor_sync(0xffffffffu, s1, d);
                q1 += __shfl_xor_sync(0xffffffffu, q1, d);
            }
            if ((tid & 31) == 0) {
                atomicAdd(&red_s[oc0], s0);
                atomicAdd(&red_s[CH + oc0], q0);
                atomicAdd(&red_s[oc0 + 1], s1);
                atomicAdd(&red_s[CH + oc0 + 1], q1);
            }
        }
    }
    __syncthreads();
    if (tid < CH) {
        atomicAdd(&g_sum[tid], red_s[tid]);
        atomicAdd(&g_sq[tid],  red_s[CH + tid]);
    }
}

// ---------------------------------------------------------------------------
// K3: per-channel BN scale/shift
// ---------------------------------------------------------------------------
__global__ void k_bnprep(const float* __restrict__ gamma, const float* __restrict__ beta)
{
    int c = threadIdx.x;
    if (c < CH) {
        const float inv_n = 1.0f / (float)NPIX;
        float mean = g_sum[c] * inv_n;
        float var  = fmaf(-mean, mean, g_sq[c] * inv_n);
        float rstd = rsqrtf(var + BN_EPS);
        float sc = rstd * gamma[c];
        g_scale[c] = sc;
        g_shift[c] = fmaf(-mean, sc, beta[c]);
    }
}

// ---------------------------------------------------------------------------
// K4: apply BN (vectorized float4)
// ---------------------------------------------------------------------------
__global__ void __launch_bounds__(256)
k_bnapply(float* __restrict__ out)
{
    int i = blockIdx.x * 256 + threadIdx.x;     // float4 index, grid covers exactly
    int c = (i >> 14) % CH;                     // (i*4 / HW) % CH, HW = 2^16
    float sc = g_scale[c], sh = g_shift[c];
    float4 v = reinterpret_cast<const float4*>(g_y)[i];
    v.x = fmaf(v.x, sc, sh);
    v.y = fmaf(v.y, sc, sh);
    v.z = fmaf(v.z, sc, sh);
    v.w = fmaf(v.w, sc, sh);
    reinterpret_cast<float4*>(out)[i] = v;
}

// ---------------------------------------------------------------------------
extern "C" void kernel_launch(void* const* d_in, const int* in_sizes, int n_in,
                              void* d_out, int out_size)
{
    const float* x      = (const float*)d_in[0];
    const float* w_qkv  = (const float*)d_in[1];
    const float* w_proj = (const float*)d_in[2];
    const float* gamma  = (const float*)d_in[3];
    const float* beta   = (const float*)d_in[4];

    const int smem1 = (CH*NTOK + 2*36*CH + 36*QSTR + 144 + 12 + 12) * (int)sizeof(float);
    cudaFuncSetAttribute(k_qkv_attn, cudaFuncAttributeMaxDynamicSharedMemorySize, smem1);

    k_zero<<<1, 128>>>();
    k_qkv_attn<<<NWIN, 256, smem1>>>(x, w_qkv);
    k_proj<<<NPIX/512, 256>>>(w_proj);
    k_bnprep<<<1, 128>>>(gamma, beta);
    k_bnapply<<<TOTAL/4/256, 256>>>((float*)d_out);
}

// round 4
// speedup vs baseline: 1.2963x; 1.2963x over previous
#include <cuda_runtime.h>

#define WS 16
#define NH 8
#define CH 96
#define DH 12          // CH / NH
#define NTOK 256       // WS*WS tokens per window
#define BATCH 8
#define IMG 256        // H = W
#define HW (IMG*IMG)   // 65536
#define NWIN 2048      // BATCH * 16 * 16
#define NPIX (BATCH*HW)        // 524288
#define TOTAL (BATCH*CH*HW)    // 50331648
#define EPS 1e-6f
#define BN_EPS 1e-5f
#define QSTR 258       // padded row stride, even -> 8B-aligned float2 rows

// scratch (device globals: allocation-free rule)
__device__ float g_out[TOTAL];   // attention output (pre-proj) scratch
__device__ float g_y[TOTAL];     // proj output (pre-BN)
__device__ float g_sum[CH];
__device__ float g_sq[CH];
__device__ float g_scale[CH];
__device__ float g_shift[CH];

// ---------------------------------------------------------------------------
// K0: zero BN accumulators (graph-replay safe)
// ---------------------------------------------------------------------------
__global__ void k_zero() {
    int t = threadIdx.x;
    if (t < CH) { g_sum[t] = 0.f; g_sq[t] = 0.f; }
}

// ---------------------------------------------------------------------------
// K1 (fused): per-window qkv GEMM + linear attention + proj + BN partial stats.
// One CTA = one 16x16 window, 256 threads, 1 CTA/SM.
// smem: x_s[96][256] (reused as w_t[96][96] in proj phase) | w_s[36][96]
//       | qkv_s[36][258] | kv[144] | ksum[12] | vsum[12] | red[192]
// ---------------------------------------------------------------------------
__global__ void __launch_bounds__(256, 1)
k_fused(const float* __restrict__ x, const float* __restrict__ w_qkv,
        const float* __restrict__ w_proj)
{
    extern __shared__ float smem[];
    float* x_s    = smem;                     // 24576 floats (phase 2: w_t 9216)
    float* w_s    = x_s + CH*NTOK;            // 3456
    float* qkv_s  = w_s + 36*CH;              // 9288
    float* kv_s   = qkv_s + 36*QSTR;          // 144
    float* ksum_s = kv_s + 144;               // 12
    float* vsum_s = ksum_s + 12;              // 12
    float* red_s  = vsum_s + 12;              // 192

    const int tid = threadIdx.x;
    const int blk = blockIdx.x;
    const int b   = blk >> 8;
    const int wIdx = blk & 255;
    const int h0 = (wIdx >> 4) * WS;
    const int w0 = (wIdx & 15) * WS;

    const int hl = tid >> 4, wl = tid & 15;
    const int pix = (h0 + hl) * IMG + (w0 + wl);

    if (tid < 2*CH) red_s[tid] = 0.f;

    // stage x window: x_s[c][n]
    {
        const float* xb = x + b*CH*HW + pix;
        #pragma unroll 8
        for (int c = 0; c < CH; c++)
            x_s[c*NTOK + tid] = xb[c*HW];
    }

    // GEMM thread mapping: 64 col-groups x 4 row-groups
    const int tx = tid & 63, ty = tid >> 6;
    const int n0 = tx * 4;        // 4 consecutive tokens
    const int r0 = ty * 9;        // 9 rows of the 36-row chunk

    for (int h = 0; h < NH; h++) {
        __syncthreads();   // protects x_s (h=0), w_s & qkv_s reuse (h>0)

        // load W chunk for this head: rows 0..11 = q, 12..23 = k, 24..35 = v
        for (int i = tid; i < 36*CH; i += 256) {
            int r = i / CH, c = i - r*CH;
            int grow = (r < 12) ? (h*DH + r)
                     : (r < 24) ? (CH + h*DH + (r - 12))
                                : (2*CH + h*DH + (r - 24));
            w_s[r*CH + c] = w_qkv[grow*CH + c];
        }
        __syncthreads();

        // 36x256 = W(36x96) @ X(96x256), 9x4 micro-tile
        float acc[9][4];
        #pragma unroll
        for (int i = 0; i < 9; i++)
            #pragma unroll
            for (int j = 0; j < 4; j++) acc[i][j] = 0.f;

        #pragma unroll 2
        for (int c = 0; c < CH; c += 2) {
            float4 a0 = *reinterpret_cast<const float4*>(&x_s[c*NTOK + n0]);
            float4 a1 = *reinterpret_cast<const float4*>(&x_s[(c+1)*NTOK + n0]);
            #pragma unroll
            for (int i = 0; i < 9; i++) {
                float2 wv = *reinterpret_cast<const float2*>(&w_s[(r0+i)*CH + c]);
                acc[i][0] = fmaf(wv.x, a0.x, acc[i][0]);
                acc[i][1] = fmaf(wv.x, a0.y, acc[i][1]);
                acc[i][2] = fmaf(wv.x, a0.z, acc[i][2]);
                acc[i][3] = fmaf(wv.x, a0.w, acc[i][3]);
                acc[i][0] = fmaf(wv.y, a1.x, acc[i][0]);
                acc[i][1] = fmaf(wv.y, a1.y, acc[i][1]);
                acc[i][2] = fmaf(wv.y, a1.z, acc[i][2]);
                acc[i][3] = fmaf(wv.y, a1.w, acc[i][3]);
            }
        }
        #pragma unroll
        for (int i = 0; i < 9; i++)
            #pragma unroll
            for (int j = 0; j < 4; j++)
                qkv_s[(r0+i)*QSTR + n0 + j] = acc[i][j];
        __syncthreads();

        // per-token l2 normalization: q kept in registers, k written back
        float qn[12];
        {
            float s = 0.f;
            #pragma unroll
            for (int m = 0; m < 12; m++) { qn[m] = qkv_s[m*QSTR + tid]; s = fmaf(qn[m], qn[m], s); }
            float r = rsqrtf(s);
            #pragma unroll
            for (int m = 0; m < 12; m++) qn[m] *= r;
        }
        {
            float kr[12]; float s = 0.f;
            #pragma unroll
            for (int m = 0; m < 12; m++) { kr[m] = qkv_s[(12+m)*QSTR + tid]; s = fmaf(kr[m], kr[m], s); }
            float r = rsqrtf(s);
            #pragma unroll
            for (int m = 0; m < 12; m++) qkv_s[(12+m)*QSTR + tid] = kr[m] * r;
        }
        __syncthreads();

        // kv[m][c] = sum_n k[m][n]*v[c][n] ; ksum[m] ; vsum[c]   (float2, 2 chains)
        if (tid < 144) {
            int m = tid / 12, c2 = tid - (tid/12)*12;
            const float2* kr = reinterpret_cast<const float2*>(&qkv_s[(12+m)*QSTR]);
            const float2* vr = reinterpret_cast<const float2*>(&qkv_s[(24+c2)*QSTR]);
            float s0 = 0.f, s1 = 0.f;
            #pragma unroll 4
            for (int n = 0; n < NTOK/2; n++) {
                float2 a = kr[n], v = vr[n];
                s0 = fmaf(a.x, v.x, s0);
                s1 = fmaf(a.y, v.y, s1);
            }
            kv_s[m*12 + c2] = s0 + s1;
        } else if (tid < 156) {
            int m = tid - 144;
            const float2* kr = reinterpret_cast<const float2*>(&qkv_s[(12+m)*QSTR]);
            float s0 = 0.f, s1 = 0.f;
            #pragma unroll 4
            for (int n = 0; n < NTOK/2; n++) { float2 a = kr[n]; s0 += a.x; s1 += a.y; }
            ksum_s[m] = s0 + s1 + EPS;
        } else if (tid < 168) {
            int c2 = tid - 156;
            const float2* vr = reinterpret_cast<const float2*>(&qkv_s[(24+c2)*QSTR]);
            float s0 = 0.f, s1 = 0.f;
            #pragma unroll 4
            for (int n = 0; n < NTOK/2; n++) { float2 a = vr[n]; s0 += a.x; s1 += a.y; }
            vsum_s[c2] = s0 + s1;
        }
        __syncthreads();

        // epilogue: out[c][n] = (q·kv[:,c] + vsum[c]) * tailor[n]
        float denom = (float)NTOK;
        #pragma unroll
        for (int m = 0; m < 12; m++) denom = fmaf(qn[m], ksum_s[m], denom);
        float tail = 1.0f / denom;

        float* ob = g_out + (b*CH + h*DH)*HW + pix;
        #pragma unroll
        for (int c2 = 0; c2 < 12; c2++) {
            float v = vsum_s[c2];
            #pragma unroll
            for (int m = 0; m < 12; m++) v = fmaf(qn[m], kv_s[m*12 + c2], v);
            ob[c2*HW] = v * tail;
        }
    }

    // ======================= proj + BN stats phase ==========================
    // x_s is dead (last read: head-7 GEMM, barriered since). Reuse as w_t[c][o].
    __syncthreads();
    float* w_t = x_s;          // 96x96 transposed proj weights
    for (int i = tid; i < CH*CH; i += 256) {
        int o = i / CH, c = i - o*CH;
        w_t[c*CH + o] = w_proj[i];
    }
    __syncthreads();

    // each thread projects its own token: reads g_out values it wrote (L1/L2 hot)
    const float* src = g_out + b*CH*HW + pix;
    float*       dst = g_y   + b*CH*HW + pix;

    #pragma unroll 1
    for (int chk = 0; chk < 3; chk++) {
        float acc[32];
        #pragma unroll
        for (int o = 0; o < 32; o++) acc[o] = 0.f;

        #pragma unroll 2
        for (int c = 0; c < CH; c++) {
            float v0 = src[c*HW];
            const float4* wt = reinterpret_cast<const float4*>(&w_t[c*CH + chk*32]);
            #pragma unroll
            for (int o4 = 0; o4 < 8; o4++) {
                float4 w = wt[o4];
                acc[o4*4+0] = fmaf(w.x, v0, acc[o4*4+0]);
                acc[o4*4+1] = fmaf(w.y, v0, acc[o4*4+1]);
                acc[o4*4+2] = fmaf(w.z, v0, acc[o4*4+2]);
                acc[o4*4+3] = fmaf(w.w, v0, acc[o4*4+3]);
            }
        }
        #pragma unroll
        for (int o = 0; o < 32; o++) {
            int oc = chk*32 + o;
            float y = acc[o];
            dst[oc*HW] = y;
            float s = y;
            float q = y * y;
            #pragma unroll
            for (int d = 16; d > 0; d >>= 1) {
                s += __shfl_xor_sync(0xffffffffu, s, d);
                q += __shfl_xor_sync(0xffffffffu, q, d);
            }
            if ((tid & 31) == 0) {
                atomicAdd(&red_s[oc], s);
                atomicAdd(&red_s[CH + oc], q);
            }
        }
    }
    __syncthreads();
    if (tid < CH) {
        atomicAdd(&g_sum[tid], red_s[tid]);
        atomicAdd(&g_sq[tid],  red_s[CH + tid]);
    }
}

// ---------------------------------------------------------------------------
// K3: per-channel BN scale/shift
// ---------------------------------------------------------------------------
__global__ void k_bnprep(const float* __restrict__ gamma, const float* __restrict__ beta)
{
    int c = threadIdx.x;
    if (c < CH) {
        const float inv_n = 1.0f / (float)NPIX;
        float mean = g_sum[c] * inv_n;
        float var  = fmaf(-mean, mean, g_sq[c] * inv_n);
        float rstd = rsqrtf(var + BN_EPS);
        float sc = rstd * gamma[c];
        g_scale[c] = sc;
        g_shift[c] = fmaf(-mean, sc, beta[c]);
    }
}

// ---------------------------------------------------------------------------
// K4: apply BN (vectorized float4)
// ---------------------------------------------------------------------------
__global__ void __launch_bounds__(256)
k_bnapply(float* __restrict__ out)
{
    int i = blockIdx.x * 256 + threadIdx.x;     // float4 index, grid covers exactly
    int c = (i >> 14) % CH;                     // (i*4 / HW) % CH, HW = 2^16
    float sc = g_scale[c], sh = g_shift[c];
    float4 v = reinterpret_cast<const float4*>(g_y)[i];
    v.x = fmaf(v.x, sc, sh);
    v.y = fmaf(v.y, sc, sh);
    v.z = fmaf(v.z, sc, sh);
    v.w = fmaf(v.w, sc, sh);
    reinterpret_cast<float4*>(out)[i] = v;
}

// ---------------------------------------------------------------------------
extern "C" void kernel_launch(void* const* d_in, const int* in_sizes, int n_in,
                              void* d_out, int out_size)
{
    const float* x      = (const float*)d_in[0];
    const float* w_qkv  = (const float*)d_in[1];
    const float* w_proj = (const float*)d_in[2];
    const float* gamma  = (const float*)d_in[3];
    const float* beta   = (const float*)d_in[4];

    const int smem1 = (CH*NTOK + 36*CH + 36*QSTR + 144 + 12 + 12 + 2*CH) * (int)sizeof(float);
    cudaFuncSetAttribute(k_fused, cudaFuncAttributeMaxDynamicSharedMemorySize, smem1);

    k_zero<<<1, 128>>>();
    k_fused<<<NWIN, 256, smem1>>>(x, w_qkv, w_proj);
    k_bnprep<<<1, 128>>>(gamma, beta);
    k_bnapply<<<TOTAL/4/256, 256>>>((float*)d_out);
}

// round 9
// speedup vs baseline: 1.5086x; 1.1638x over previous
#include <cuda_runtime.h>
#include <cuda_bf16.h>
#include <mma.h>
#include <cstdint>

using namespace nvcuda;

#define WS 16
#define NH 8
#define CH 96
#define DH 12
#define NTOK 256
#define BATCH 8
#define IMG 256
#define HW (IMG*IMG)
#define NWIN 2048
#define NPIX (BATCH*HW)        // 524288
#define TOTAL (BATCH*CH*HW)    // 50331648
#define EPS 1e-6f
#define BN_EPS 1e-5f
#define QSTR 260               // attn smem row stride (mult of 4 -> 16B rows)

// ---------------- device scratch (allocation-free rule) ---------------------
__device__ float g_qkv[3*CH*NPIX];   // qkv pre-attention  [row 0..287][b][hw]
__device__ float g_out[TOTAL];       // attention output   [b][c][hw]
__device__ float g_y[TOTAL];         // proj output        [b][c][hw]
__device__ float g_sum[CH];
__device__ float g_sq[CH];
__device__ float g_scale[CH];
__device__ float g_shift[CH];

// ---------------- GEMM smem layout (bytes) ----------------------------------
#define WLDM 104                         // bf16 elems per W row (208 B, 16B mult)
#define XLDM 136                         // bf16 elems per X row (272 B)
#define SLDM 136                         // f32 stage ldm (544 B, 32B mult)
#define SM_WHI   0
#define SM_WLO   (96*WLDM*2)             // 19968
#define SM_XHI   (2*96*WLDM*2)           // 39936
#define SM_XLO   (SM_XHI + 96*XLDM*2)    // 66048
#define SM_STAGE (SM_XLO + 96*XLDM*2)    // 92160
#define SM_RED   (SM_STAGE + 96*SLDM*4)  // 144384
#define SM_GEMM_TOTAL (SM_RED + 768)     // 145152

// ---------------------------------------------------------------------------
// K0: zero BN accumulators (graph-replay safe)
// ---------------------------------------------------------------------------
__global__ void k_zero() {
    int t = threadIdx.x;
    if (t < CH) { g_sum[t] = 0.f; g_sq[t] = 0.f; }
}

// ---------------------------------------------------------------------------
// WMMA GEMM (bf16 3-term split, fp32 accum):
//   per CTA: Y[96, 128tok] = W[96,96] @ X[96,128tok] for nslices W slices.
// qkv_mode=1: in = x, W = w_qkv (3 slices), out rows stride NPIX.
// qkv_mode=0: in = g_out, W = w_proj (1 slice), out = g_y, + BN stats.
// 8 warps: (wid&1) -> M half (3 tiles of 16), (wid>>1) -> N quarter (2 tiles).
// ---------------------------------------------------------------------------
__global__ void __launch_bounds__(256)
k_gemm(const float* __restrict__ in, const float* __restrict__ w,
       float* __restrict__ outp, int nslices, int qkv_mode)
{
    extern __shared__ char smem[];
    __nv_bfloat16* wHi = (__nv_bfloat16*)(smem + SM_WHI);
    __nv_bfloat16* wLo = (__nv_bfloat16*)(smem + SM_WLO);
    __nv_bfloat16* xHi = (__nv_bfloat16*)(smem + SM_XHI);
    __nv_bfloat16* xLo = (__nv_bfloat16*)(smem + SM_XLO);
    float* stage = (float*)(smem + SM_STAGE);
    float* red_s = (float*)(smem + SM_RED);

    const int tid = threadIdx.x;
    const int wid = tid >> 5;

    const int b   = blockIdx.x >> 9;       // 512 tiles per batch image
    const int hw0 = (blockIdx.x & 511) << 7;

    if (tid < 2*CH) red_s[tid] = 0.f;

    // load + split X tile once: [k = channel][n = token]
    {
        const float* xb = in + (size_t)b*CH*HW + hw0;
        for (int i = tid; i < CH*128; i += 256) {
            int k = i >> 7, n = i & 127;
            float v = xb[(size_t)k*HW + n];
            __nv_bfloat16 h = __float2bfloat16(v);
            xHi[k*XLDM + n] = h;
            xLo[k*XLDM + n] = __float2bfloat16(v - __bfloat162float(h));
        }
    }

    const int mrow = wid & 1;    // 0..1 -> M tiles [mrow*3, mrow*3+2]
    const int ncol = wid >> 1;   // 0..3 -> N tiles [ncol*2, ncol*2+1]

    for (int s = 0; s < nslices; s++) {
        __syncthreads();    // X/stage from previous phase safe; W reuse
        // load + split W slice [96x96]
        {
            const float* ws = w + (size_t)s*CH*CH;
            for (int i = tid; i < CH*CH; i += 256) {
                int r = i / CH, c = i - r*CH;
                float v = ws[i];
                __nv_bfloat16 h = __float2bfloat16(v);
                wHi[r*WLDM + c] = h;
                wLo[r*WLDM + c] = __float2bfloat16(v - __bfloat162float(h));
            }
        }
        __syncthreads();

        wmma::fragment<wmma::accumulator, 16, 16, 16, float> acc[3][2];
        #pragma unroll
        for (int mt = 0; mt < 3; mt++) {
            wmma::fill_fragment(acc[mt][0], 0.f);
            wmma::fill_fragment(acc[mt][1], 0.f);
        }

        const __nv_bfloat16* aT[3] = { wHi, wHi, wLo };
        const __nv_bfloat16* bT[3] = { xHi, xLo, xHi };

        #pragma unroll
        for (int t = 0; t < 3; t++) {
            #pragma unroll
            for (int kt = 0; kt < 6; kt++) {
                wmma::fragment<wmma::matrix_b, 16, 16, 16, __nv_bfloat16, wmma::row_major> bf0, bf1;
                wmma::load_matrix_sync(bf0, bT[t] + kt*16*XLDM + (ncol*2)*16,     XLDM);
                wmma::load_matrix_sync(bf1, bT[t] + kt*16*XLDM + (ncol*2 + 1)*16, XLDM);
                #pragma unroll
                for (int mt = 0; mt < 3; mt++) {
                    wmma::fragment<wmma::matrix_a, 16, 16, 16, __nv_bfloat16, wmma::row_major> af;
                    wmma::load_matrix_sync(af, aT[t] + (mrow*3 + mt)*16*WLDM + kt*16, WLDM);
                    wmma::mma_sync(acc[mt][0], af, bf0, acc[mt][0]);
                    wmma::mma_sync(acc[mt][1], af, bf1, acc[mt][1]);
                }
            }
        }

        // stage fp32 result for coalesced global write
        #pragma unroll
        for (int mt = 0; mt < 3; mt++)
            #pragma unroll
            for (int nt = 0; nt < 2; nt++)
                wmma::store_matrix_sync(stage + (mrow*3 + mt)*16*SLDM + (ncol*2 + nt)*16,
                                        acc[mt][nt], SLDM, wmma::mem_row_major);
        __syncthreads();

        float* out_base;
        size_t rstride;
        if (qkv_mode) { out_base = outp + (size_t)(s*CH)*NPIX + (size_t)b*HW + hw0; rstride = NPIX; }
        else          { out_base = outp + (size_t)b*CH*HW + hw0;                    rstride = HW;   }

        for (int e = tid; e < CH*128; e += 256) {
            int ch = e >> 7, j = e & 127;
            float v = stage[ch*SLDM + j];
            out_base[(size_t)ch*rstride + j] = v;
            if (!qkv_mode) {
                float ss = v, qq = v*v;
                #pragma unroll
                for (int d = 16; d > 0; d >>= 1) {
                    ss += __shfl_xor_sync(0xffffffffu, ss, d);
                    qq += __shfl_xor_sync(0xffffffffu, qq, d);
                }
                if ((tid & 31) == 0) {
                    atomicAdd(&red_s[ch], ss);
                    atomicAdd(&red_s[CH + ch], qq);
                }
            }
        }
    }

    if (!qkv_mode) {
        __syncthreads();
        if (tid < CH) {
            atomicAdd(&g_sum[tid], red_s[tid]);
            atomicAdd(&g_sq[tid],  red_s[CH + tid]);
        }
    }
}

// ---------------------------------------------------------------------------
// K_attn: per-window linear attention on precomputed qkv. One CTA per window.
// (math identical to the verified scalar kernel)
// ---------------------------------------------------------------------------
__global__ void __launch_bounds__(256)
k_attn()
{
    extern __shared__ float smf[];
    float* qkv_s  = smf;                  // 36 x 260
    float* kv_s   = qkv_s + 36*QSTR;      // 144
    float* ksum_s = kv_s + 144;           // 12
    float* vsum_s = ksum_s + 12;          // 12

    const int tid = threadIdx.x;
    const int blk = blockIdx.x;
    const int b   = blk >> 8;
    const int wIdx = blk & 255;
    const int h0 = (wIdx >> 4) * WS;
    const int w0 = (wIdx & 15) * WS;
    const int hl = tid >> 4, wl = tid & 15;
    const int pix = (h0 + hl) * IMG + (w0 + wl);

    for (int h = 0; h < NH; h++) {
        __syncthreads();
        // load 36 qkv rows for this head (float4 over 4-token groups)
        for (int i = tid; i < 36*64; i += 256) {
            int r = i >> 6, g = i & 63;
            int n = g << 2;
            int grow = (r < 12) ? (h*DH + r)
                     : (r < 24) ? (CH + h*DH + (r - 12))
                                : (2*CH + h*DH + (r - 24));
            int p4 = (h0 + (n >> 4)) * IMG + w0 + (n & 15);
            float4 v = *reinterpret_cast<const float4*>(
                g_qkv + (size_t)grow*NPIX + (size_t)b*HW + p4);
            *reinterpret_cast<float4*>(&qkv_s[r*QSTR + n]) = v;
        }
        __syncthreads();

        // l2 norm: q in regs, k in place
        float qn[12];
        {
            float s = 0.f;
            #pragma unroll
            for (int m = 0; m < 12; m++) { qn[m] = qkv_s[m*QSTR + tid]; s = fmaf(qn[m], qn[m], s); }
            float r = rsqrtf(s);
            #pragma unroll
            for (int m = 0; m < 12; m++) qn[m] *= r;
        }
        {
            float kr[12]; float s = 0.f;
            #pragma unroll
            for (int m = 0; m < 12; m++) { kr[m] = qkv_s[(12+m)*QSTR + tid]; s = fmaf(kr[m], kr[m], s); }
            float r = rsqrtf(s);
            #pragma unroll
            for (int m = 0; m < 12; m++) qkv_s[(12+m)*QSTR + tid] = kr[m] * r;
        }
        __syncthreads();

        // kv / ksum / vsum
        if (tid < 144) {
            int m = tid / 12, c2 = tid - (tid/12)*12;
            const float2* kr = reinterpret_cast<const float2*>(&qkv_s[(12+m)*QSTR]);
            const float2* vr = reinterpret_cast<const float2*>(&qkv_s[(24+c2)*QSTR]);
            float s0 = 0.f, s1 = 0.f;
            #pragma unroll 4
            for (int n = 0; n < NTOK/2; n++) {
                float2 a = kr[n], v = vr[n];
                s0 = fmaf(a.x, v.x, s0);
                s1 = fmaf(a.y, v.y, s1);
            }
            kv_s[m*12 + c2] = s0 + s1;
        } else if (tid < 156) {
            int m = tid - 144;
            const float2* kr = reinterpret_cast<const float2*>(&qkv_s[(12+m)*QSTR]);
            float s0 = 0.f, s1 = 0.f;
            #pragma unroll 4
            for (int n = 0; n < NTOK/2; n++) { float2 a = kr[n]; s0 += a.x; s1 += a.y; }
            ksum_s[m] = s0 + s1 + EPS;
        } else if (tid < 168) {
            int c2 = tid - 156;
            const float2* vr = reinterpret_cast<const float2*>(&qkv_s[(24+c2)*QSTR]);
            float s0 = 0.f, s1 = 0.f;
            #pragma unroll 4
            for (int n = 0; n < NTOK/2; n++) { float2 a = vr[n]; s0 += a.x; s1 += a.y; }
            vsum_s[c2] = s0 + s1;
        }
        __syncthreads();

        float denom = (float)NTOK;
        #pragma unroll
        for (int m = 0; m < 12; m++) denom = fmaf(qn[m], ksum_s[m], denom);
        float tail = 1.0f / denom;

        float* ob = g_out + (size_t)(b*CH + h*DH)*HW + pix;
        #pragma unroll
        for (int c2 = 0; c2 < 12; c2++) {
            float v = vsum_s[c2];
            #pragma unroll
            for (int m = 0; m < 12; m++) v = fmaf(qn[m], kv_s[m*12 + c2], v);
            ob[(size_t)c2*HW] = v * tail;
        }
    }
}

// ---------------------------------------------------------------------------
__global__ void k_bnprep(const float* __restrict__ gamma, const float* __restrict__ beta)
{
    int c = threadIdx.x;
    if (c < CH) {
        const float inv_n = 1.0f / (float)NPIX;
        float mean = g_sum[c] * inv_n;
        float var  = fmaf(-mean, mean, g_sq[c] * inv_n);
        float rstd = rsqrtf(var + BN_EPS);
        float sc = rstd * gamma[c];
        g_scale[c] = sc;
        g_shift[c] = fmaf(-mean, sc, beta[c]);
    }
}

__global__ void __launch_bounds__(256)
k_bnapply(float* __restrict__ out)
{
    int i = blockIdx.x * 256 + threadIdx.x;
    int c = (i >> 14) % CH;
    float sc = g_scale[c], sh = g_shift[c];
    float4 v = reinterpret_cast<const float4*>(g_y)[i];
    v.x = fmaf(v.x, sc, sh);
    v.y = fmaf(v.y, sc, sh);
    v.z = fmaf(v.z, sc, sh);
    v.w = fmaf(v.w, sc, sh);
    reinterpret_cast<float4*>(out)[i] = v;
}

// ---------------------------------------------------------------------------
extern "C" void kernel_launch(void* const* d_in, const int* in_sizes, int n_in,
                              void* d_out, int out_size)
{
    const float* x      = (const float*)d_in[0];
    const float* w_qkv  = (const float*)d_in[1];
    const float* w_proj = (const float*)d_in[2];
    const float* gamma  = (const float*)d_in[3];
    const float* beta   = (const float*)d_in[4];

    cudaFuncSetAttribute(k_gemm, cudaFuncAttributeMaxDynamicSharedMemorySize, SM_GEMM_TOTAL);

    float* gqkv;  cudaGetSymbolAddress((void**)&gqkv, g_qkv);
    float* gout;  cudaGetSymbolAddress((void**)&gout, g_out);
    float* gy;    cudaGetSymbolAddress((void**)&gy,   g_y);

    const int smem_attn = (36*QSTR + 144 + 12 + 12) * (int)sizeof(float);

    k_zero<<<1, 128>>>();
    k_gemm<<<4096, 256, SM_GEMM_TOTAL>>>(x, w_qkv, gqkv, 3, 1);
    k_attn<<<NWIN, 256, smem_attn>>>();
    k_gemm<<<4096, 256, SM_GEMM_TOTAL>>>(gout, w_proj, gy, 1, 0);
    k_bnprep<<<1, 128>>>(gamma, beta);
    k_bnapply<<<TOTAL/4/256, 256>>>((float*)d_out);
}

// round 10
// speedup vs baseline: 2.2416x; 1.4859x over previous
#include <cuda_runtime.h>
#include <cuda_bf16.h>
#include <mma.h>
#include <cstdint>

using namespace nvcuda;

#define WS 16
#define NH 8
#define CH 96
#define DH 12
#define NTOK 256
#define BATCH 8
#define IMG 256
#define HW (IMG*IMG)
#define NWIN 2048
#define NPIX (BATCH*HW)        // 524288
#define TOTAL (BATCH*CH*HW)    // 50331648
#define EPS 1e-6f
#define BN_EPS 1e-5f
#define QSTR 260               // attn smem row stride (mult of 4 -> 16B rows)

// ---------------- device scratch (allocation-free rule) ---------------------
__device__ float g_qkv[3*CH*NPIX];   // qkv pre-attention  [row 0..287][b][hw]
__device__ float g_out[TOTAL];       // attention output   [b][c][hw]
__device__ float g_y[TOTAL];         // proj output        [b][c][hw]
__device__ float g_sum[CH];
__device__ float g_sq[CH];
__device__ float g_scale[CH];
__device__ float g_shift[CH];

// ---------------- GEMM smem layout (bytes) ----------------------------------
#define WLDM 104                         // bf16 elems per W row (208 B)
#define XLDM 136                         // bf16 elems per X row (272 B)
#define SM_WHI   0
#define SM_WLO   (96*WLDM*2)             // 19968
#define SM_XHI   (2*96*WLDM*2)           // 39936
#define SM_XLO   (SM_XHI + 96*XLDM*2)    // 66048
#define SM_GEMM_TOTAL (SM_XLO + 96*XLDM*2)   // 92160  -> 2 CTAs/SM

// ---------------------------------------------------------------------------
__global__ void k_zero() {
    int t = threadIdx.x;
    if (t < CH) { g_sum[t] = 0.f; g_sq[t] = 0.f; }
}

// ---------------------------------------------------------------------------
// WMMA GEMM (bf16 3-term split, fp32 accum), 2 CTAs/SM:
//   per CTA: Y[96, 128tok] = W[96,96] @ X[96,128tok] for nslices W slices.
// qkv_mode=1: in = x, W = w_qkv (3 slices), out rows stride NPIX.
// qkv_mode=0: in = g_out, W = w_proj (1 slice), out = g_y.
// Fragments stored straight to global (no smem stage).
// ---------------------------------------------------------------------------
__global__ void __launch_bounds__(256, 2)
k_gemm(const float* __restrict__ in, const float* __restrict__ w,
       float* __restrict__ outp, int nslices, int qkv_mode)
{
    extern __shared__ char smem[];
    __nv_bfloat16* wHi = (__nv_bfloat16*)(smem + SM_WHI);
    __nv_bfloat16* wLo = (__nv_bfloat16*)(smem + SM_WLO);
    __nv_bfloat16* xHi = (__nv_bfloat16*)(smem + SM_XHI);
    __nv_bfloat16* xLo = (__nv_bfloat16*)(smem + SM_XLO);

    const int tid = threadIdx.x;
    const int wid = tid >> 5;

    const int b   = blockIdx.x >> 9;       // 512 tiles per batch image
    const int hw0 = (blockIdx.x & 511) << 7;

    // load + split X tile once: [k = channel][n = token]
    {
        const float* xb = in + (size_t)b*CH*HW + hw0;
        for (int i = tid; i < CH*128; i += 256) {
            int k = i >> 7, n = i & 127;
            float v = xb[(size_t)k*HW + n];
            __nv_bfloat16 h = __float2bfloat16(v);
            xHi[k*XLDM + n] = h;
            xLo[k*XLDM + n] = __float2bfloat16(v - __bfloat162float(h));
        }
    }

    const int mrow = wid & 1;    // 0..1 -> M tiles [mrow*3, mrow*3+2]
    const int ncol = wid >> 1;   // 0..3 -> N tiles [ncol*2, ncol*2+1]

    for (int s = 0; s < nslices; s++) {
        __syncthreads();    // X safe / W reuse boundary
        // load + split W slice [96x96]
        {
            const float* ws = w + (size_t)s*CH*CH;
            for (int i = tid; i < CH*CH; i += 256) {
                int r = i / CH, c = i - r*CH;
                float v = ws[i];
                __nv_bfloat16 h = __float2bfloat16(v);
                wHi[r*WLDM + c] = h;
                wLo[r*WLDM + c] = __float2bfloat16(v - __bfloat162float(h));
            }
        }
        __syncthreads();

        wmma::fragment<wmma::accumulator, 16, 16, 16, float> acc[3][2];
        #pragma unroll
        for (int mt = 0; mt < 3; mt++) {
            wmma::fill_fragment(acc[mt][0], 0.f);
            wmma::fill_fragment(acc[mt][1], 0.f);
        }

        const __nv_bfloat16* aT[3] = { wHi, wHi, wLo };
        const __nv_bfloat16* bT[3] = { xHi, xLo, xHi };

        #pragma unroll 1
        for (int t = 0; t < 3; t++) {
            #pragma unroll 1
            for (int kt = 0; kt < 6; kt++) {
                wmma::fragment<wmma::matrix_b, 16, 16, 16, __nv_bfloat16, wmma::row_major> bf0, bf1;
                wmma::load_matrix_sync(bf0, bT[t] + kt*16*XLDM + (ncol*2)*16,     XLDM);
                wmma::load_matrix_sync(bf1, bT[t] + kt*16*XLDM + (ncol*2 + 1)*16, XLDM);
                #pragma unroll
                for (int mt = 0; mt < 3; mt++) {
                    wmma::fragment<wmma::matrix_a, 16, 16, 16, __nv_bfloat16, wmma::row_major> af;
                    wmma::load_matrix_sync(af, aT[t] + (mrow*3 + mt)*16*WLDM + kt*16, WLDM);
                    wmma::mma_sync(acc[mt][0], af, bf0, acc[mt][0]);
                    wmma::mma_sync(acc[mt][1], af, bf1, acc[mt][1]);
                }
            }
        }

        // store fragments directly to global
        float* out_base;
        unsigned rstride;
        if (qkv_mode) { out_base = outp + (size_t)(s*CH)*NPIX + (size_t)b*HW + hw0; rstride = NPIX; }
        else          { out_base = outp + (size_t)b*CH*HW + hw0;                    rstride = HW;   }

        #pragma unroll
        for (int mt = 0; mt < 3; mt++)
            #pragma unroll
            for (int nt = 0; nt < 2; nt++)
                wmma::store_matrix_sync(out_base + (size_t)(mrow*3 + mt)*16*rstride
                                                 + (ncol*2 + nt)*16,
                                        acc[mt][nt], rstride, wmma::mem_row_major);
    }
}

// ---------------------------------------------------------------------------
// K_attn: per-(window, head-quad) linear attention. grid (2048, 2).
// ---------------------------------------------------------------------------
__global__ void __launch_bounds__(256)
k_attn()
{
    extern __shared__ float smf[];
    float* qkv_s  = smf;                  // 36 x 260
    float* kv_s   = qkv_s + 36*QSTR;      // 144
    float* ksum_s = kv_s + 144;           // 12
    float* vsum_s = ksum_s + 12;          // 12

    const int tid = threadIdx.x;
    const int blk = blockIdx.x;
    const int b   = blk >> 8;
    const int wIdx = blk & 255;
    const int h0 = (wIdx >> 4) * WS;
    const int w0 = (wIdx & 15) * WS;
    const int hl = tid >> 4, wl = tid & 15;
    const int pix = (h0 + hl) * IMG + (w0 + wl);
    const int hbase = blockIdx.y * 4;

    for (int hh = 0; hh < 4; hh++) {
        const int h = hbase + hh;
        __syncthreads();
        // load 36 qkv rows for this head (float4 over 4-token groups)
        for (int i = tid; i < 36*64; i += 256) {
            int r = i >> 6, g = i & 63;
            int n = g << 2;
            int grow = (r < 12) ? (h*DH + r)
                     : (r < 24) ? (CH + h*DH + (r - 12))
                                : (2*CH + h*DH + (r - 24));
            int p4 = (h0 + (n >> 4)) * IMG + w0 + (n & 15);
            float4 v = *reinterpret_cast<const float4*>(
                g_qkv + (size_t)grow*NPIX + (size_t)b*HW + p4);
            *reinterpret_cast<float4*>(&qkv_s[r*QSTR + n]) = v;
        }
        __syncthreads();

        // l2 norm: q in regs, k in place
        float qn[12];
        {
            float s = 0.f;
            #pragma unroll
            for (int m = 0; m < 12; m++) { qn[m] = qkv_s[m*QSTR + tid]; s = fmaf(qn[m], qn[m], s); }
            float r = rsqrtf(s);
            #pragma unroll
            for (int m = 0; m < 12; m++) qn[m] *= r;
        }
        {
            float kr[12]; float s = 0.f;
            #pragma unroll
            for (int m = 0; m < 12; m++) { kr[m] = qkv_s[(12+m)*QSTR + tid]; s = fmaf(kr[m], kr[m], s); }
            float r = rsqrtf(s);
            #pragma unroll
            for (int m = 0; m < 12; m++) qkv_s[(12+m)*QSTR + tid] = kr[m] * r;
        }
        __syncthreads();

        // kv / ksum / vsum
        if (tid < 144) {
            int m = tid / 12, c2 = tid - (tid/12)*12;
            const float2* kr = reinterpret_cast<const float2*>(&qkv_s[(12+m)*QSTR]);
            const float2* vr = reinterpret_cast<const float2*>(&qkv_s[(24+c2)*QSTR]);
            float s0 = 0.f, s1 = 0.f;
            #pragma unroll 4
            for (int n = 0; n < NTOK/2; n++) {
                float2 a = kr[n], v = vr[n];
                s0 = fmaf(a.x, v.x, s0);
                s1 = fmaf(a.y, v.y, s1);
            }
            kv_s[m*12 + c2] = s0 + s1;
        } else if (tid < 156) {
            int m = tid - 144;
            const float2* kr = reinterpret_cast<const float2*>(&qkv_s[(12+m)*QSTR]);
            float s0 = 0.f, s1 = 0.f;
            #pragma unroll 4
            for (int n = 0; n < NTOK/2; n++) { float2 a = kr[n]; s0 += a.x; s1 += a.y; }
            ksum_s[m] = s0 + s1 + EPS;
        } else if (tid < 168) {
            int c2 = tid - 156;
            const float2* vr = reinterpret_cast<const float2*>(&qkv_s[(24+c2)*QSTR]);
            float s0 = 0.f, s1 = 0.f;
            #pragma unroll 4
            for (int n = 0; n < NTOK/2; n++) { float2 a = vr[n]; s0 += a.x; s1 += a.y; }
            vsum_s[c2] = s0 + s1;
        }
        __syncthreads();

        float denom = (float)NTOK;
        #pragma unroll
        for (int m = 0; m < 12; m++) denom = fmaf(qn[m], ksum_s[m], denom);
        float tail = 1.0f / denom;

        float* ob = g_out + (size_t)(b*CH + h*DH)*HW + pix;
        #pragma unroll
        for (int c2 = 0; c2 < 12; c2++) {
            float v = vsum_s[c2];
            #pragma unroll
            for (int m = 0; m < 12; m++) v = fmaf(qn[m], kv_s[m*12 + c2], v);
            ob[(size_t)c2*HW] = v * tail;
        }
    }
}

// ---------------------------------------------------------------------------
// K_bnstats: per-channel sum / sumsq over g_y. grid (96, 8).
// ---------------------------------------------------------------------------
__global__ void __launch_bounds__(256)
k_bnstats()
{
    __shared__ float s_s[8], s_q[8];
    const int c = blockIdx.x, b = blockIdx.y;
    const int tid = threadIdx.x;

    const float4* p = reinterpret_cast<const float4*>(g_y + (size_t)(b*CH + c)*HW);
    float s = 0.f, q = 0.f;
    for (int i = tid; i < HW/4; i += 256) {
        float4 v = p[i];
        s += v.x + v.y + v.z + v.w;
        q += v.x*v.x + v.y*v.y + v.z*v.z + v.w*v.w;
    }
    #pragma unroll
    for (int d = 16; d > 0; d >>= 1) {
        s += __shfl_xor_sync(0xffffffffu, s, d);
        q += __shfl_xor_sync(0xffffffffu, q, d);
    }
    if ((tid & 31) == 0) { s_s[tid >> 5] = s; s_q[tid >> 5] = q; }
    __syncthreads();
    if (tid == 0) {
        float ts = 0.f, tq = 0.f;
        #pragma unroll
        for (int i = 0; i < 8; i++) { ts += s_s[i]; tq += s_q[i]; }
        atomicAdd(&g_sum[c], ts);
        atomicAdd(&g_sq[c],  tq);
    }
}

// ---------------------------------------------------------------------------
__global__ void k_bnprep(const float* __restrict__ gamma, const float* __restrict__ beta)
{
    int c = threadIdx.x;
    if (c < CH) {
        const float inv_n = 1.0f / (float)NPIX;
        float mean = g_sum[c] * inv_n;
        float var  = fmaf(-mean, mean, g_sq[c] * inv_n);
        float rstd = rsqrtf(var + BN_EPS);
        float sc = rstd * gamma[c];
        g_scale[c] = sc;
        g_shift[c] = fmaf(-mean, sc, beta[c]);
    }
}

__global__ void __launch_bounds__(256)
k_bnapply(float* __restrict__ out)
{
    int i = blockIdx.x * 256 + threadIdx.x;
    int c = (i >> 14) % CH;
    float sc = g_scale[c], sh = g_shift[c];
    float4 v = reinterpret_cast<const float4*>(g_y)[i];
    v.x = fmaf(v.x, sc, sh);
    v.y = fmaf(v.y, sc, sh);
    v.z = fmaf(v.z, sc, sh);
    v.w = fmaf(v.w, sc, sh);
    reinterpret_cast<float4*>(out)[i] = v;
}

// ---------------------------------------------------------------------------
extern "C" void kernel_launch(void* const* d_in, const int* in_sizes, int n_in,
                              void* d_out, int out_size)
{
    const float* x      = (const float*)d_in[0];
    const float* w_qkv  = (const float*)d_in[1];
    const float* w_proj = (const float*)d_in[2];
    const float* gamma  = (const float*)d_in[3];
    const float* beta   = (const float*)d_in[4];

    cudaFuncSetAttribute(k_gemm, cudaFuncAttributeMaxDynamicSharedMemorySize, SM_GEMM_TOTAL);

    float* gqkv;  cudaGetSymbolAddress((void**)&gqkv, g_qkv);
    float* gout;  cudaGetSymbolAddress((void**)&gout, g_out);
    float* gy;    cudaGetSymbolAddress((void**)&gy,   g_y);

    const int smem_attn = (36*QSTR + 144 + 12 + 12) * (int)sizeof(float);

    k_zero<<<1, 128>>>();
    k_gemm<<<4096, 256, SM_GEMM_TOTAL>>>(x, w_qkv, gqkv, 3, 1);
    k_attn<<<dim3(NWIN, 2), 256, smem_attn>>>();
    k_gemm<<<4096, 256, SM_GEMM_TOTAL>>>(gout, w_proj, gy, 1, 0);
    k_bnstats<<<dim3(CH, BATCH), 256>>>();
    k_bnprep<<<1, 128>>>(gamma, beta);
    k_bnapply<<<TOTAL/4/256, 256>>>((float*)d_out);
}

// round 11
// speedup vs baseline: 2.3769x; 1.0604x over previous
#include <cuda_runtime.h>
#include <cuda_bf16.h>
#include <mma.h>
#include <cstdint>

using namespace nvcuda;

#define WS 16
#define NH 8
#define CH 96
#define DH 12
#define NTOK 256
#define BATCH 8
#define IMG 256
#define HW (IMG*IMG)
#define NWIN 2048
#define NPIX (BATCH*HW)        // 524288
#define TOTAL (BATCH*CH*HW)    // 50331648
#define EPS 1e-6f
#define BN_EPS 1e-5f
#define QSTR 260               // attn smem row stride

#define WLDM 104               // bf16 elems per W row (208 B)
#define XLDM 136               // bf16 elems per X row (272 B)

// ---------------- device scratch (allocation-free rule) ---------------------
__device__ float g_qkv[3*CH*NPIX];   // qkv pre-attention  [row 0..287][b][hw]
__device__ float g_out[TOTAL];       // attention output   [b][c][hw]
__device__ float g_y[TOTAL];         // proj output        [b][c][hw]
__device__ float g_sum[CH];
__device__ float g_sq[CH];
__device__ float g_scale[CH];
__device__ float g_shift[CH];
__device__ __nv_bfloat16 g_wHi[4*CH*WLDM];   // slices 0..2 = qkv, 3 = proj
__device__ __nv_bfloat16 g_wLo[4*CH*WLDM];

// ---------------- GEMM smem: X split only ------------------------------------
#define SM_XHI 0
#define SM_XLO (96*XLDM*2)                 // 26112
#define SM_GEMM_TOTAL (2*96*XLDM*2)        // 52224 -> 3 CTAs/SM

// ---------------------------------------------------------------------------
__global__ void k_zero() {
    int t = threadIdx.x;
    if (t < CH) { g_sum[t] = 0.f; g_sq[t] = 0.f; }
}

// ---------------------------------------------------------------------------
// K_wsplit: pre-split all weight slices to bf16 hi/lo in global scratch.
// ---------------------------------------------------------------------------
__global__ void k_wsplit(const float* __restrict__ w_qkv, const float* __restrict__ w_proj)
{
    int i = blockIdx.x * 256 + threadIdx.x;          // 4*96*96 = 36864
    if (i >= 4*CH*CH) return;
    int s = i / (CH*CH);
    int r = (i / CH) % CH;
    int c = i % CH;
    float v = (s < 3) ? w_qkv[(size_t)s*CH*CH + r*CH + c] : w_proj[r*CH + c];
    __nv_bfloat16 h = __float2bfloat16(v);
    g_wHi[(size_t)s*CH*WLDM + r*WLDM + c] = h;
    g_wLo[(size_t)s*CH*WLDM + r*WLDM + c] = __float2bfloat16(v - __bfloat162float(h));
}

// ---------------------------------------------------------------------------
// WMMA GEMM (bf16 3-term split, fp32 accum), 3 CTAs/SM, W frags from global L1:
//   per CTA: Y[96, 128tok] = W[96,96] @ X[96,128tok] for nslices W slices.
// ---------------------------------------------------------------------------
__global__ void __launch_bounds__(256, 3)
k_gemm(const float* __restrict__ in, float* __restrict__ outp,
       int nslices, int wbase, int qkv_mode)
{
    extern __shared__ char smem[];
    __nv_bfloat16* xHi = (__nv_bfloat16*)(smem + SM_XHI);
    __nv_bfloat16* xLo = (__nv_bfloat16*)(smem + SM_XLO);

    const int tid = threadIdx.x;
    const int wid = tid >> 5;

    const int b   = blockIdx.x >> 9;       // 512 tiles per batch image
    const int hw0 = (blockIdx.x & 511) << 7;

    // load + split X tile once: [k = channel][n = token]
    {
        const float* xb = in + (size_t)b*CH*HW + hw0;
        for (int i = tid; i < CH*128; i += 256) {
            int k = i >> 7, n = i & 127;
            float v = xb[(size_t)k*HW + n];
            __nv_bfloat16 h = __float2bfloat16(v);
            xHi[k*XLDM + n] = h;
            xLo[k*XLDM + n] = __float2bfloat16(v - __bfloat162float(h));
        }
    }
    __syncthreads();

    const int mrow = wid & 1;    // 0..1 -> M tiles [mrow*3, mrow*3+2]
    const int ncol = wid >> 1;   // 0..3 -> N tiles [ncol*2, ncol*2+1]

    for (int s = 0; s < nslices; s++) {
        const __nv_bfloat16* wHi = g_wHi + (size_t)(wbase + s)*CH*WLDM;
        const __nv_bfloat16* wLo = g_wLo + (size_t)(wbase + s)*CH*WLDM;

        wmma::fragment<wmma::accumulator, 16, 16, 16, float> acc[3][2];
        #pragma unroll
        for (int mt = 0; mt < 3; mt++) {
            wmma::fill_fragment(acc[mt][0], 0.f);
            wmma::fill_fragment(acc[mt][1], 0.f);
        }

        const __nv_bfloat16* aT[3] = { wHi, wHi, wLo };
        const __nv_bfloat16* bT[3] = { xHi, xLo, xHi };

        #pragma unroll 1
        for (int t = 0; t < 3; t++) {
            #pragma unroll 1
            for (int kt = 0; kt < 6; kt++) {
                wmma::fragment<wmma::matrix_b, 16, 16, 16, __nv_bfloat16, wmma::row_major> bf0, bf1;
                wmma::load_matrix_sync(bf0, bT[t] + kt*16*XLDM + (ncol*2)*16,     XLDM);
                wmma::load_matrix_sync(bf1, bT[t] + kt*16*XLDM + (ncol*2 + 1)*16, XLDM);
                #pragma unroll
                for (int mt = 0; mt < 3; mt++) {
                    wmma::fragment<wmma::matrix_a, 16, 16, 16, __nv_bfloat16, wmma::row_major> af;
                    wmma::load_matrix_sync(af, aT[t] + (mrow*3 + mt)*16*WLDM + kt*16, WLDM);
                    wmma::mma_sync(acc[mt][0], af, bf0, acc[mt][0]);
                    wmma::mma_sync(acc[mt][1], af, bf1, acc[mt][1]);
                }
            }
        }

        // store fragments directly to global
        float* out_base;
        unsigned rstride;
        if (qkv_mode) { out_base = outp + (size_t)(s*CH)*NPIX + (size_t)b*HW + hw0; rstride = NPIX; }
        else          { out_base = outp + (size_t)b*CH*HW + hw0;                    rstride = HW;   }

        #pragma unroll
        for (int mt = 0; mt < 3; mt++)
            #pragma unroll
            for (int nt = 0; nt < 2; nt++)
                wmma::store_matrix_sync(out_base + (size_t)(mrow*3 + mt)*16*rstride
                                                 + (ncol*2 + nt)*16,
                                        acc[mt][nt], rstride, wmma::mem_row_major);
    }
}

// ---------------------------------------------------------------------------
// K_attn: per-(window, head-pair) linear attention. grid (2048, 4).
// ---------------------------------------------------------------------------
__global__ void __launch_bounds__(256)
k_attn()
{
    extern __shared__ float smf[];
    float* qkv_s  = smf;                  // 36 x 260
    float* kv_s   = qkv_s + 36*QSTR;      // 144
    float* ksum_s = kv_s + 144;           // 12
    float* vsum_s = ksum_s + 12;          // 12

    const int tid = threadIdx.x;
    const int blk = blockIdx.x;
    const int b   = blk >> 8;
    const int wIdx = blk & 255;
    const int h0 = (wIdx >> 4) * WS;
    const int w0 = (wIdx & 15) * WS;
    const int hl = tid >> 4, wl = tid & 15;
    const int pix = (h0 + hl) * IMG + (w0 + wl);
    const int hbase = blockIdx.y * 2;

    for (int hh = 0; hh < 2; hh++) {
        const int h = hbase + hh;
        __syncthreads();
        // load 36 qkv rows for this head (float4 over 4-token groups)
        for (int i = tid; i < 36*64; i += 256) {
            int r = i >> 6, g = i & 63;
            int n = g << 2;
            int grow = (r < 12) ? (h*DH + r)
                     : (r < 24) ? (CH + h*DH + (r - 12))
                                : (2*CH + h*DH + (r - 24));
            int p4 = (h0 + (n >> 4)) * IMG + w0 + (n & 15);
            float4 v = *reinterpret_cast<const float4*>(
                g_qkv + (size_t)grow*NPIX + (size_t)b*HW + p4);
            *reinterpret_cast<float4*>(&qkv_s[r*QSTR + n]) = v;
        }
        __syncthreads();

        // l2 norm: q in regs, k in place
        float qn[12];
        {
            float s = 0.f;
            #pragma unroll
            for (int m = 0; m < 12; m++) { qn[m] = qkv_s[m*QSTR + tid]; s = fmaf(qn[m], qn[m], s); }
            float r = rsqrtf(s);
            #pragma unroll
            for (int m = 0; m < 12; m++) qn[m] *= r;
        }
        {
            float kr[12]; float s = 0.f;
            #pragma unroll
            for (int m = 0; m < 12; m++) { kr[m] = qkv_s[(12+m)*QSTR + tid]; s = fmaf(kr[m], kr[m], s); }
            float r = rsqrtf(s);
            #pragma unroll
            for (int m = 0; m < 12; m++) qkv_s[(12+m)*QSTR + tid] = kr[m] * r;
        }
        __syncthreads();

        // kv / ksum / vsum
        if (tid < 144) {
            int m = tid / 12, c2 = tid - (tid/12)*12;
            const float2* kr = reinterpret_cast<const float2*>(&qkv_s[(12+m)*QSTR]);
            const float2* vr = reinterpret_cast<const float2*>(&qkv_s[(24+c2)*QSTR]);
            float s0 = 0.f, s1 = 0.f;
            #pragma unroll 4
            for (int n = 0; n < NTOK/2; n++) {
                float2 a = kr[n], v = vr[n];
                s0 = fmaf(a.x, v.x, s0);
                s1 = fmaf(a.y, v.y, s1);
            }
            kv_s[m*12 + c2] = s0 + s1;
        } else if (tid < 156) {
            int m = tid - 144;
            const float2* kr = reinterpret_cast<const float2*>(&qkv_s[(12+m)*QSTR]);
            float s0 = 0.f, s1 = 0.f;
            #pragma unroll 4
            for (int n = 0; n < NTOK/2; n++) { float2 a = kr[n]; s0 += a.x; s1 += a.y; }
            ksum_s[m] = s0 + s1 + EPS;
        } else if (tid < 168) {
            int c2 = tid - 156;
            const float2* vr = reinterpret_cast<const float2*>(&qkv_s[(24+c2)*QSTR]);
            float s0 = 0.f, s1 = 0.f;
            #pragma unroll 4
            for (int n = 0; n < NTOK/2; n++) { float2 a = vr[n]; s0 += a.x; s1 += a.y; }
            vsum_s[c2] = s0 + s1;
        }
        __syncthreads();

        float denom = (float)NTOK;
        #pragma unroll
        for (int m = 0; m < 12; m++) denom = fmaf(qn[m], ksum_s[m], denom);
        float tail = 1.0f / denom;

        float* ob = g_out + (size_t)(b*CH + h*DH)*HW + pix;
        #pragma unroll
        for (int c2 = 0; c2 < 12; c2++) {
            float v = vsum_s[c2];
            #pragma unroll
            for (int m = 0; m < 12; m++) v = fmaf(qn[m], kv_s[m*12 + c2], v);
            ob[(size_t)c2*HW] = v * tail;
        }
    }
}

// ---------------------------------------------------------------------------
// K_bnstats: per-channel sum / sumsq over g_y. grid (96, 8).
// ---------------------------------------------------------------------------
__global__ void __launch_bounds__(256)
k_bnstats()
{
    __shared__ float s_s[8], s_q[8];
    const int c = blockIdx.x, b = blockIdx.y;
    const int tid = threadIdx.x;

    const float4* p = reinterpret_cast<const float4*>(g_y + (size_t)(b*CH + c)*HW);
    float s = 0.f, q = 0.f;
    for (int i = tid; i < HW/4; i += 256) {
        float4 v = p[i];
        s += v.x + v.y + v.z + v.w;
        q += v.x*v.x + v.y*v.y + v.z*v.z + v.w*v.w;
    }
    #pragma unroll
    for (int d = 16; d > 0; d >>= 1) {
        s += __shfl_xor_sync(0xffffffffu, s, d);
        q += __shfl_xor_sync(0xffffffffu, q, d);
    }
    if ((tid & 31) == 0) { s_s[tid >> 5] = s; s_q[tid >> 5] = q; }
    __syncthreads();
    if (tid == 0) {
        float ts = 0.f, tq = 0.f;
        #pragma unroll
        for (int i = 0; i < 8; i++) { ts += s_s[i]; tq += s_q[i]; }
        atomicAdd(&g_sum[c], ts);
        atomicAdd(&g_sq[c],  tq);
    }
}

// ---------------------------------------------------------------------------
__global__ void k_bnprep(const float* __restrict__ gamma, const float* __restrict__ beta)
{
    int c = threadIdx.x;
    if (c < CH) {
        const float inv_n = 1.0f / (float)NPIX;
        float mean = g_sum[c] * inv_n;
        float var  = fmaf(-mean, mean, g_sq[c] * inv_n);
        float rstd = rsqrtf(var + BN_EPS);
        float sc = rstd * gamma[c];
        g_scale[c] = sc;
        g_shift[c] = fmaf(-mean, sc, beta[c]);
    }
}

__global__ void __launch_bounds__(256)
k_bnapply(float* __restrict__ out)
{
    int i = blockIdx.x * 256 + threadIdx.x;
    int c = (i >> 14) % CH;
    float sc = g_scale[c], sh = g_shift[c];
    float4 v = reinterpret_cast<const float4*>(g_y)[i];
    v.x = fmaf(v.x, sc, sh);
    v.y = fmaf(v.y, sc, sh);
    v.z = fmaf(v.z, sc, sh);
    v.w = fmaf(v.w, sc, sh);
    reinterpret_cast<float4*>(out)[i] = v;
}

// ---------------------------------------------------------------------------
extern "C" void kernel_launch(void* const* d_in, const int* in_sizes, int n_in,
                              void* d_out, int out_size)
{
    const float* x      = (const float*)d_in[0];
    const float* w_qkv  = (const float*)d_in[1];
    const float* w_proj = (const float*)d_in[2];
    const float* gamma  = (const float*)d_in[3];
    const float* beta   = (const float*)d_in[4];

    cudaFuncSetAttribute(k_gemm, cudaFuncAttributeMaxDynamicSharedMemorySize, SM_GEMM_TOTAL);

    float* gqkv;  cudaGetSymbolAddress((void**)&gqkv, g_qkv);
    float* gout;  cudaGetSymbolAddress((void**)&gout, g_out);
    float* gy;    cudaGetSymbolAddress((void**)&gy,   g_y);

    const int smem_attn = (36*QSTR + 144 + 12 + 12) * (int)sizeof(float);

    k_zero<<<1, 128>>>();
    k_wsplit<<<144, 256>>>(x ? (const float*)d_in[1] : nullptr, w_proj);
    k_gemm<<<4096, 256, SM_GEMM_TOTAL>>>(x, gqkv, 3, 0, 1);
    k_attn<<<dim3(NWIN, 4), 256, smem_attn>>>();
    k_gemm<<<4096, 256, SM_GEMM_TOTAL>>>(gout, gy, 1, 3, 0);
    k_bnstats<<<dim3(CH, BATCH), 256>>>();
    k_bnprep<<<1, 128>>>(gamma, beta);
    k_bnapply<<<TOTAL/4/256, 256>>>((float*)d_out);
}

// round 13
// speedup vs baseline: 2.4076x; 1.0129x over previous
#include <cuda_runtime.h>
#include <cuda_bf16.h>
#include <mma.h>
#include <cstdint>

using namespace nvcuda;

#define WS 16
#define NH 8
#define CH 96
#define DH 12
#define NTOK 256
#define BATCH 8
#define IMG 256
#define HW (IMG*IMG)
#define NWIN 2048
#define NPIX (BATCH*HW)        // 524288
#define TOTAL (BATCH*CH*HW)    // 50331648
#define EPS 1e-6f
#define BN_EPS 1e-5f
#define QSTR 260               // attn smem row stride (16B-aligned rows)

#define WLDM 104               // bf16 elems per W row (208 B)
#define XLDM 136               // bf16 elems per X row (272 B)

// ---------------- device scratch (allocation-free rule) ---------------------
__device__ float g_qkv[3*CH*NPIX];   // qkv pre-attention  [row 0..287][b][hw]
__device__ float g_out[TOTAL];       // attention output   [b][c][hw]
__device__ float g_y[TOTAL];         // proj output        [b][c][hw]
__device__ float g_sum[CH];
__device__ float g_sq[CH];
__device__ float g_scale[CH];
__device__ float g_shift[CH];
__device__ __nv_bfloat16 g_wHi[4*CH*WLDM];   // slices 0..2 = qkv, 3 = proj
__device__ __nv_bfloat16 g_wLo[4*CH*WLDM];

// ---------------- GEMM smem: X split only ------------------------------------
#define SM_XHI 0
#define SM_XLO (96*XLDM*2)                 // 26112
#define SM_GEMM_TOTAL (2*96*XLDM*2)        // 52224 -> 3 CTAs/SM

// ---------------------------------------------------------------------------
__global__ void k_zero() {
    int t = threadIdx.x;
    if (t < CH) { g_sum[t] = 0.f; g_sq[t] = 0.f; }
}

// ---------------------------------------------------------------------------
// K_wsplit: pre-split all weight slices to bf16 hi/lo in global scratch.
// ---------------------------------------------------------------------------
__global__ void k_wsplit(const float* __restrict__ w_qkv, const float* __restrict__ w_proj)
{
    int i = blockIdx.x * 256 + threadIdx.x;          // 4*96*96 = 36864
    if (i >= 4*CH*CH) return;
    int s = i / (CH*CH);
    int r = (i / CH) % CH;
    int c = i % CH;
    float v = (s < 3) ? w_qkv[(size_t)s*CH*CH + r*CH + c] : w_proj[r*CH + c];
    __nv_bfloat16 h = __float2bfloat16(v);
    g_wHi[(size_t)s*CH*WLDM + r*WLDM + c] = h;
    g_wLo[(size_t)s*CH*WLDM + r*WLDM + c] = __float2bfloat16(v - __bfloat162float(h));
}

// ---------------------------------------------------------------------------
// WMMA GEMM (bf16 3-term split, fp32 accum), 3 CTAs/SM, W frags from global L1:
//   per CTA: Y[96, 128tok] = W[96,96] @ X[96,128tok] for nslices W slices.
// ---------------------------------------------------------------------------
__global__ void __launch_bounds__(256, 3)
k_gemm(const float* __restrict__ in, float* __restrict__ outp,
       int nslices, int wbase, int qkv_mode)
{
    extern __shared__ char smem[];
    __nv_bfloat16* xHi = (__nv_bfloat16*)(smem + SM_XHI);
    __nv_bfloat16* xLo = (__nv_bfloat16*)(smem + SM_XLO);

    const int tid = threadIdx.x;
    const int wid = tid >> 5;

    const int b   = blockIdx.x >> 9;       // 512 tiles per batch image
    const int hw0 = (blockIdx.x & 511) << 7;

    // load + split X tile once: [k = channel][n = token]
    {
        const float* xb = in + (size_t)b*CH*HW + hw0;
        for (int i = tid; i < CH*128; i += 256) {
            int k = i >> 7, n = i & 127;
            float v = xb[(size_t)k*HW + n];
            __nv_bfloat16 h = __float2bfloat16(v);
            xHi[k*XLDM + n] = h;
            xLo[k*XLDM + n] = __float2bfloat16(v - __bfloat162float(h));
        }
    }
    __syncthreads();

    const int mrow = wid & 1;    // 0..1 -> M tiles [mrow*3, mrow*3+2]
    const int ncol = wid >> 1;   // 0..3 -> N tiles [ncol*2, ncol*2+1]

    for (int s = 0; s < nslices; s++) {
        const __nv_bfloat16* wHi = g_wHi + (size_t)(wbase + s)*CH*WLDM;
        const __nv_bfloat16* wLo = g_wLo + (size_t)(wbase + s)*CH*WLDM;

        wmma::fragment<wmma::accumulator, 16, 16, 16, float> acc[3][2];
        #pragma unroll
        for (int mt = 0; mt < 3; mt++) {
            wmma::fill_fragment(acc[mt][0], 0.f);
            wmma::fill_fragment(acc[mt][1], 0.f);
        }

        const __nv_bfloat16* aT[3] = { wHi, wHi, wLo };
        const __nv_bfloat16* bT[3] = { xHi, xLo, xHi };

        #pragma unroll 1
        for (int t = 0; t < 3; t++) {
            #pragma unroll 1
            for (int kt = 0; kt < 6; kt++) {
                wmma::fragment<wmma::matrix_b, 16, 16, 16, __nv_bfloat16, wmma::row_major> bf0, bf1;
                wmma::load_matrix_sync(bf0, bT[t] + kt*16*XLDM + (ncol*2)*16,     XLDM);
                wmma::load_matrix_sync(bf1, bT[t] + kt*16*XLDM + (ncol*2 + 1)*16, XLDM);
                #pragma unroll
                for (int mt = 0; mt < 3; mt++) {
                    wmma::fragment<wmma::matrix_a, 16, 16, 16, __nv_bfloat16, wmma::row_major> af;
                    wmma::load_matrix_sync(af, aT[t] + (mrow*3 + mt)*16*WLDM + kt*16, WLDM);
                    wmma::mma_sync(acc[mt][0], af, bf0, acc[mt][0]);
                    wmma::mma_sync(acc[mt][1], af, bf1, acc[mt][1]);
                }
            }
        }

        // store fragments directly to global
        float* out_base;
        unsigned rstride;
        if (qkv_mode) { out_base = outp + (size_t)(s*CH)*NPIX + (size_t)b*HW + hw0; rstride = NPIX; }
        else          { out_base = outp + (size_t)b*CH*HW + hw0;                    rstride = HW;   }

        #pragma unroll
        for (int mt = 0; mt < 3; mt++)
            #pragma unroll
            for (int nt = 0; nt < 2; nt++)
                wmma::store_matrix_sync(out_base + (size_t)(mrow*3 + mt)*16*rstride
                                                 + (ncol*2 + nt)*16,
                                        acc[mt][nt], rstride, wmma::mem_row_major);
    }
}

// ---------------------------------------------------------------------------
// K_attn: one CTA per (window, head). grid (2048, 8). float4 reductions.
// ---------------------------------------------------------------------------
__global__ void __launch_bounds__(256, 4)
k_attn()
{
    extern __shared__ float smf[];
    float* qkv_s  = smf;                  // 36 x 260
    float* kv_s   = qkv_s + 36*QSTR;      // 144
    float* ksum_s = kv_s + 144;           // 12
    float* vsum_s = ksum_s + 12;          // 12

    const int tid = threadIdx.x;
    const int blk = blockIdx.x;
    const int b   = blk >> 8;
    const int wIdx = blk & 255;
    const int h0 = (wIdx >> 4) * WS;
    const int w0 = (wIdx & 15) * WS;
    const int hl = tid >> 4, wl = tid & 15;
    const int pix = (h0 + hl) * IMG + (w0 + wl);
    const int h = blockIdx.y;

    // load 36 qkv rows for this head (float4 over 4-token groups)
    for (int i = tid; i < 36*64; i += 256) {
        int r = i >> 6, g = i & 63;
        int n = g << 2;
        int grow = (r < 12) ? (h*DH + r)
                 : (r < 24) ? (CH + h*DH + (r - 12))
                            : (2*CH + h*DH + (r - 24));
        int p4 = (h0 + (n >> 4)) * IMG + w0 + (n & 15);
        float4 v = *reinterpret_cast<const float4*>(
            g_qkv + (size_t)grow*NPIX + (size_t)b*HW + p4);
        *reinterpret_cast<float4*>(&qkv_s[r*QSTR + n]) = v;
    }
    __syncthreads();

    // l2 norm: q in regs, k in place
    float qn[12];
    {
        float s = 0.f;
        #pragma unroll
        for (int m = 0; m < 12; m++) { qn[m] = qkv_s[m*QSTR + tid]; s = fmaf(qn[m], qn[m], s); }
        float r = rsqrtf(s);
        #pragma unroll
        for (int m = 0; m < 12; m++) qn[m] *= r;
    }
    {
        float kr[12]; float s = 0.f;
        #pragma unroll
        for (int m = 0; m < 12; m++) { kr[m] = qkv_s[(12+m)*QSTR + tid]; s = fmaf(kr[m], kr[m], s); }
        float r = rsqrtf(s);
        #pragma unroll
        for (int m = 0; m < 12; m++) qkv_s[(12+m)*QSTR + tid] = kr[m] * r;
    }
    __syncthreads();

    // kv / ksum / vsum  (float4, 4 chains)
    if (tid < 144) {
        int m = tid / 12, c2 = tid - (tid/12)*12;
        const float4* kr = reinterpret_cast<const float4*>(&qkv_s[(12+m)*QSTR]);
        const float4* vr = reinterpret_cast<const float4*>(&qkv_s[(24+c2)*QSTR]);
        float s0 = 0.f, s1 = 0.f, s2 = 0.f, s3 = 0.f;
        #pragma unroll 4
        for (int n = 0; n < NTOK/4; n++) {
            float4 a = kr[n], v = vr[n];
            s0 = fmaf(a.x, v.x, s0);
            s1 = fmaf(a.y, v.y, s1);
            s2 = fmaf(a.z, v.z, s2);
            s3 = fmaf(a.w, v.w, s3);
        }
        kv_s[m*12 + c2] = (s0 + s1) + (s2 + s3);
    } else if (tid < 156) {
        int m = tid - 144;
        const float4* kr = reinterpret_cast<const float4*>(&qkv_s[(12+m)*QSTR]);
        float s0 = 0.f, s1 = 0.f, s2 = 0.f, s3 = 0.f;
        #pragma unroll 4
        for (int n = 0; n < NTOK/4; n++) {
            float4 a = kr[n];
            s0 += a.x; s1 += a.y; s2 += a.z; s3 += a.w;
        }
        ksum_s[m] = (s0 + s1) + (s2 + s3) + EPS;
    } else if (tid < 168) {
        int c2 = tid - 156;
        const float4* vr = reinterpret_cast<const float4*>(&qkv_s[(24+c2)*QSTR]);
        float s0 = 0.f, s1 = 0.f, s2 = 0.f, s3 = 0.f;
        #pragma unroll 4
        for (int n = 0; n < NTOK/4; n++) {
            float4 a = vr[n];
            s0 += a.x; s1 += a.y; s2 += a.z; s3 += a.w;
        }
        vsum_s[c2] = (s0 + s1) + (s2 + s3);
    }
    __syncthreads();

    float denom = (float)NTOK;
    #pragma unroll
    for (int m = 0; m < 12; m++) denom = fmaf(qn[m], ksum_s[m], denom);
    float tail = 1.0f / denom;

    float* ob = g_out + (size_t)(b*CH + h*DH)*HW + pix;
    #pragma unroll
    for (int c2 = 0; c2 < 12; c2++) {
        float v = vsum_s[c2];
        #pragma unroll
        for (int m = 0; m < 12; m++) v = fmaf(qn[m], kv_s[m*12 + c2], v);
        ob[(size_t)c2*HW] = v * tail;
    }
}

// ---------------------------------------------------------------------------
// K_bnstats: per-channel sum / sumsq over g_y. grid (96, 8).
// ---------------------------------------------------------------------------
__global__ void __launch_bounds__(256)
k_bnstats()
{
    __shared__ float s_s[8], s_q[8];
    const int c = blockIdx.x, b = blockIdx.y;
    const int tid = threadIdx.x;

    const float4* p = reinterpret_cast<const float4*>(g_y + (size_t)(b*CH + c)*HW);
    float s = 0.f, q = 0.f;
    for (int i = tid; i < HW/4; i += 256) {
        float4 v = p[i];
        s += v.x + v.y + v.z + v.w;
        q += v.x*v.x + v.y*v.y + v.z*v.z + v.w*v.w;
    }
    #pragma unroll
    for (int d = 16; d > 0; d >>= 1) {
        s += __shfl_xor_sync(0xffffffffu, s, d);
        q += __shfl_xor_sync(0xffffffffu, q, d);
    }
    if ((tid & 31) == 0) { s_s[tid >> 5] = s; s_q[tid >> 5] = q; }
    __syncthreads();
    if (tid == 0) {
        float ts = 0.f, tq = 0.f;
        #pragma unroll
        for (int i = 0; i < 8; i++) { ts += s_s[i]; tq += s_q[i]; }
        atomicAdd(&g_sum[c], ts);
        atomicAdd(&g_sq[c],  tq);
    }
}

// ---------------------------------------------------------------------------
__global__ void k_bnprep(const float* __restrict__ gamma, const float* __restrict__ beta)
{
    int c = threadIdx.x;
    if (c < CH) {
        const float inv_n = 1.0f / (float)NPIX;
        float mean = g_sum[c] * inv_n;
        float var  = fmaf(-mean, mean, g_sq[c] * inv_n);
        float rstd = rsqrtf(var + BN_EPS);
        float sc = rstd * gamma[c];
        g_scale[c] = sc;
        g_shift[c] = fmaf(-mean, sc, beta[c]);
    }
}

__global__ void __launch_bounds__(256)
k_bnapply(float* __restrict__ out)
{
    int i = blockIdx.x * 256 + threadIdx.x;
    int c = (i >> 14) % CH;
    float sc = g_scale[c], sh = g_shift[c];
    float4 v = reinterpret_cast<const float4*>(g_y)[i];
    v.x = fmaf(v.x, sc, sh);
    v.y = fmaf(v.y, sc, sh);
    v.z = fmaf(v.z, sc, sh);
    v.w = fmaf(v.w, sc, sh);
    reinterpret_cast<float4*>(out)[i] = v;
}

// ---------------------------------------------------------------------------
extern "C" void kernel_launch(void* const* d_in, const int* in_sizes, int n_in,
                              void* d_out, int out_size)
{
    const float* x      = (const float*)d_in[0];
    const float* w_qkv  = (const float*)d_in[1];
    const float* w_proj = (const float*)d_in[2];
    const float* gamma  = (const float*)d_in[3];
    const float* beta   = (const float*)d_in[4];

    const int smem_attn = (36*QSTR + 144 + 12 + 12) * (int)sizeof(float);
    cudaFuncSetAttribute(k_gemm, cudaFuncAttributeMaxDynamicSharedMemorySize, SM_GEMM_TOTAL);
    cudaFuncSetAttribute(k_attn, cudaFuncAttributeMaxDynamicSharedMemorySize, smem_attn);

    float* gqkv;  cudaGetSymbolAddress((void**)&gqkv, g_qkv);
    float* gout;  cudaGetSymbolAddress((void**)&gout, g_out);
    float* gy;    cudaGetSymbolAddress((void**)&gy,   g_y);

    k_zero<<<1, 128>>>();
    k_wsplit<<<144, 256>>>(w_qkv, w_proj);
    k_gemm<<<4096, 256, SM_GEMM_TOTAL>>>(x, gqkv, 3, 0, 1);
    k_attn<<<dim3(NWIN, NH), 256, smem_attn>>>();
    k_gemm<<<4096, 256, SM_GEMM_TOTAL>>>(gout, gy, 1, 3, 0);
    k_bnstats<<<dim3(CH, BATCH), 256>>>();
    k_bnprep<<<1, 128>>>(gamma, beta);
    k_bnapply<<<TOTAL/4/256, 256>>>((float*)d_out);
}

// round 14
// speedup vs baseline: 2.5388x; 1.0545x over previous
#include <cuda_runtime.h>
#include <cuda_bf16.h>
#include <mma.h>
#include <cstdint>

using namespace nvcuda;

#define WS 16
#define NH 8
#define CH 96
#define DH 12
#define NTOK 256
#define BATCH 8
#define IMG 256
#define HW (IMG*IMG)
#define NWIN 2048
#define NPIX (BATCH*HW)        // 524288
#define TOTAL (BATCH*CH*HW)    // 50331648
#define EPS 1e-6f
#define BN_EPS 1e-5f
#define QSTR 260               // attn smem row stride (16B-aligned rows)

#define WLDM 104               // bf16 elems per W row (208 B)
#define XLDM 136               // bf16 elems per X row (272 B)

// ---------------- device scratch (allocation-free rule) ---------------------
__device__ float g_qkv[3*CH*NPIX];   // qkv pre-attention  [row 0..287][b][hw]
__device__ float g_out[TOTAL];       // attention output   [b][c][hw]
__device__ float g_y[TOTAL];         // proj output        [b][c][hw]
__device__ float g_sum[CH];
__device__ float g_sq[CH];
__device__ float g_scale[CH];
__device__ float g_shift[CH];
__device__ __nv_bfloat16 g_wHi[4*CH*WLDM];   // slices 0..2 = qkv, 3 = proj
__device__ __nv_bfloat16 g_wLo[4*CH*WLDM];

// ---------------- GEMM smem: X split only ------------------------------------
#define SM_XHI 0
#define SM_XLO (96*XLDM*2)                 // 26112
#define SM_GEMM_TOTAL (2*96*XLDM*2)        // 52224 -> 3 CTAs/SM

// attn smem floats: qkv rows + kv/ksum/vsum + partial buffers (stride 17)
#define ATTN_SMEM_FLOATS (36*QSTR + 144 + 12 + 12 + 144*17 + 12*17 + 12*17)

// ---------------------------------------------------------------------------
__global__ void k_zero() {
    int t = threadIdx.x;
    if (t < CH) { g_sum[t] = 0.f; g_sq[t] = 0.f; }
}

// ---------------------------------------------------------------------------
// K_wsplit: pre-split all weight slices to bf16 hi/lo in global scratch.
// ---------------------------------------------------------------------------
__global__ void k_wsplit(const float* __restrict__ w_qkv, const float* __restrict__ w_proj)
{
    int i = blockIdx.x * 256 + threadIdx.x;          // 4*96*96 = 36864
    if (i >= 4*CH*CH) return;
    int s = i / (CH*CH);
    int r = (i / CH) % CH;
    int c = i % CH;
    float v = (s < 3) ? w_qkv[(size_t)s*CH*CH + r*CH + c] : w_proj[r*CH + c];
    __nv_bfloat16 h = __float2bfloat16(v);
    g_wHi[(size_t)s*CH*WLDM + r*WLDM + c] = h;
    g_wLo[(size_t)s*CH*WLDM + r*WLDM + c] = __float2bfloat16(v - __bfloat162float(h));
}

// ---------------------------------------------------------------------------
// WMMA GEMM (bf16 3-term split, fp32 accum), 3 CTAs/SM, W frags from global L1:
//   per CTA: Y[96, 128tok] = W[96,96] @ X[96,128tok] for nslices W slices.
// ---------------------------------------------------------------------------
__global__ void __launch_bounds__(256, 3)
k_gemm(const float* __restrict__ in, float* __restrict__ outp,
       int nslices, int wbase, int qkv_mode)
{
    extern __shared__ char smem[];
    __nv_bfloat16* xHi = (__nv_bfloat16*)(smem + SM_XHI);
    __nv_bfloat16* xLo = (__nv_bfloat16*)(smem + SM_XLO);

    const int tid = threadIdx.x;
    const int wid = tid >> 5;

    const int b   = blockIdx.x >> 9;       // 512 tiles per batch image
    const int hw0 = (blockIdx.x & 511) << 7;

    // load + split X tile once: [k = channel][n = token]
    {
        const float* xb = in + (size_t)b*CH*HW + hw0;
        for (int i = tid; i < CH*128; i += 256) {
            int k = i >> 7, n = i & 127;
            float v = xb[(size_t)k*HW + n];
            __nv_bfloat16 h = __float2bfloat16(v);
            xHi[k*XLDM + n] = h;
            xLo[k*XLDM + n] = __float2bfloat16(v - __bfloat162float(h));
        }
    }
    __syncthreads();

    const int mrow = wid & 1;    // 0..1 -> M tiles [mrow*3, mrow*3+2]
    const int ncol = wid >> 1;   // 0..3 -> N tiles [ncol*2, ncol*2+1]

    for (int s = 0; s < nslices; s++) {
        const __nv_bfloat16* wHi = g_wHi + (size_t)(wbase + s)*CH*WLDM;
        const __nv_bfloat16* wLo = g_wLo + (size_t)(wbase + s)*CH*WLDM;

        wmma::fragment<wmma::accumulator, 16, 16, 16, float> acc[3][2];
        #pragma unroll
        for (int mt = 0; mt < 3; mt++) {
            wmma::fill_fragment(acc[mt][0], 0.f);
            wmma::fill_fragment(acc[mt][1], 0.f);
        }

        const __nv_bfloat16* aT[3] = { wHi, wHi, wLo };
        const __nv_bfloat16* bT[3] = { xHi, xLo, xHi };

        #pragma unroll 1
        for (int t = 0; t < 3; t++) {
            #pragma unroll 1
            for (int kt = 0; kt < 6; kt++) {
                wmma::fragment<wmma::matrix_b, 16, 16, 16, __nv_bfloat16, wmma::row_major> bf0, bf1;
                wmma::load_matrix_sync(bf0, bT[t] + kt*16*XLDM + (ncol*2)*16,     XLDM);
                wmma::load_matrix_sync(bf1, bT[t] + kt*16*XLDM + (ncol*2 + 1)*16, XLDM);
                #pragma unroll
                for (int mt = 0; mt < 3; mt++) {
                    wmma::fragment<wmma::matrix_a, 16, 16, 16, __nv_bfloat16, wmma::row_major> af;
                    wmma::load_matrix_sync(af, aT[t] + (mrow*3 + mt)*16*WLDM + kt*16, WLDM);
                    wmma::mma_sync(acc[mt][0], af, bf0, acc[mt][0]);
                    wmma::mma_sync(acc[mt][1], af, bf1, acc[mt][1]);
                }
            }
        }

        // store fragments directly to global
        float* out_base;
        unsigned rstride;
        if (qkv_mode) { out_base = outp + (size_t)(s*CH)*NPIX + (size_t)b*HW + hw0; rstride = NPIX; }
        else          { out_base = outp + (size_t)b*CH*HW + hw0;                    rstride = HW;   }

        #pragma unroll
        for (int mt = 0; mt < 3; mt++)
            #pragma unroll
            for (int nt = 0; nt < 2; nt++)
                wmma::store_matrix_sync(out_base + (size_t)(mrow*3 + mt)*16*rstride
                                                 + (ncol*2 + nt)*16,
                                        acc[mt][nt], rstride, wmma::mem_row_major);
    }
}

// ---------------------------------------------------------------------------
// K_attn: one CTA per (window, head). grid (2048, 8).
// kv phase uses (3m x 3c) blocking x 16-way token split -> 3x fewer LDS bytes.
// ---------------------------------------------------------------------------
__global__ void __launch_bounds__(256, 4)
k_attn()
{
    extern __shared__ float smf[];
    float* qkv_s  = smf;                        // 36 x 260
    float* kv_s   = qkv_s + 36*QSTR;            // 144
    float* ksum_s = kv_s + 144;                 // 12
    float* vsum_s = ksum_s + 12;                // 12
    float* pkv    = vsum_s + 12;                // 144 x 17
    float* pks    = pkv + 144*17;               // 12 x 17
    float* pvs    = pks + 12*17;                // 12 x 17

    const int tid = threadIdx.x;
    const int blk = blockIdx.x;
    const int b   = blk >> 8;
    const int wIdx = blk & 255;
    const int h0 = (wIdx >> 4) * WS;
    const int w0 = (wIdx & 15) * WS;
    const int hl = tid >> 4, wl = tid & 15;
    const int pix = (h0 + hl) * IMG + (w0 + wl);
    const int h = blockIdx.y;

    // load 36 qkv rows for this head (float4 over 4-token groups)
    for (int i = tid; i < 36*64; i += 256) {
        int r = i >> 6, g = i & 63;
        int n = g << 2;
        int grow = (r < 12) ? (h*DH + r)
                 : (r < 24) ? (CH + h*DH + (r - 12))
                            : (2*CH + h*DH + (r - 24));
        int p4 = (h0 + (n >> 4)) * IMG + w0 + (n & 15);
        float4 v = *reinterpret_cast<const float4*>(
            g_qkv + (size_t)grow*NPIX + (size_t)b*HW + p4);
        *reinterpret_cast<float4*>(&qkv_s[r*QSTR + n]) = v;
    }
    __syncthreads();

    // l2 norm: q and k normalized IN PLACE (q reloaded in epilogue)
    {
        float t[12]; float s = 0.f;
        #pragma unroll
        for (int m = 0; m < 12; m++) { t[m] = qkv_s[m*QSTR + tid]; s = fmaf(t[m], t[m], s); }
        float r = rsqrtf(s);
        #pragma unroll
        for (int m = 0; m < 12; m++) qkv_s[m*QSTR + tid] = t[m] * r;
    }
    {
        float t[12]; float s = 0.f;
        #pragma unroll
        for (int m = 0; m < 12; m++) { t[m] = qkv_s[(12+m)*QSTR + tid]; s = fmaf(t[m], t[m], s); }
        float r = rsqrtf(s);
        #pragma unroll
        for (int m = 0; m < 12; m++) qkv_s[(12+m)*QSTR + tid] = t[m] * r;
    }
    __syncthreads();

    // kv blocked: thread = (blk16 = (mg,cg), g = token-chunk of 16)
    {
        const int bk = tid & 15;         // block id
        const int g  = tid >> 4;         // 0..15
        const int mg = bk >> 2, cg = bk & 3;
        const int col0 = g * 16;

        float acc[3][3] = {{0.f,0.f,0.f},{0.f,0.f,0.f},{0.f,0.f,0.f}};
        float ks[3] = {0.f,0.f,0.f}, vs[3] = {0.f,0.f,0.f};

        #pragma unroll
        for (int it = 0; it < 4; it++) {
            float4 kk[3], vv[3];
            #pragma unroll
            for (int i = 0; i < 3; i++)
                kk[i] = *reinterpret_cast<const float4*>(&qkv_s[(12 + mg*3 + i)*QSTR + col0 + it*4]);
            #pragma unroll
            for (int j = 0; j < 3; j++)
                vv[j] = *reinterpret_cast<const float4*>(&qkv_s[(24 + cg*3 + j)*QSTR + col0 + it*4]);
            #pragma unroll
            for (int i = 0; i < 3; i++)
                #pragma unroll
                for (int j = 0; j < 3; j++) {
                    acc[i][j] = fmaf(kk[i].x, vv[j].x, acc[i][j]);
                    acc[i][j] = fmaf(kk[i].y, vv[j].y, acc[i][j]);
                    acc[i][j] = fmaf(kk[i].z, vv[j].z, acc[i][j]);
                    acc[i][j] = fmaf(kk[i].w, vv[j].w, acc[i][j]);
                }
            if (cg == 0) {
                #pragma unroll
                for (int i = 0; i < 3; i++)
                    ks[i] += (kk[i].x + kk[i].y) + (kk[i].z + kk[i].w);
            }
            if (mg == 0) {
                #pragma unroll
                for (int j = 0; j < 3; j++)
                    vs[j] += (vv[j].x + vv[j].y) + (vv[j].z + vv[j].w);
            }
        }
        #pragma unroll
        for (int i = 0; i < 3; i++)
            #pragma unroll
            for (int j = 0; j < 3; j++)
                pkv[((mg*3 + i)*12 + cg*3 + j)*17 + g] = acc[i][j];
        if (cg == 0) {
            #pragma unroll
            for (int i = 0; i < 3; i++) pks[(mg*3 + i)*17 + g] = ks[i];
        }
        if (mg == 0) {
            #pragma unroll
            for (int j = 0; j < 3; j++) pvs[(cg*3 + j)*17 + g] = vs[j];
        }
    }
    __syncthreads();

    // fold partials
    if (tid < 144) {
        float s = 0.f;
        #pragma unroll
        for (int u = 0; u < 16; u++) s += pkv[tid*17 + u];
        kv_s[tid] = s;
    } else if (tid < 156) {
        int m = tid - 144;
        float s = 0.f;
        #pragma unroll
        for (int u = 0; u < 16; u++) s += pks[m*17 + u];
        ksum_s[m] = s + EPS;
    } else if (tid < 168) {
        int c2 = tid - 156;
        float s = 0.f;
        #pragma unroll
        for (int u = 0; u < 16; u++) s += pvs[c2*17 + u];
        vsum_s[c2] = s;
    }
    __syncthreads();

    // epilogue: reload normalized q for this token
    float qn[12];
    #pragma unroll
    for (int m = 0; m < 12; m++) qn[m] = qkv_s[m*QSTR + tid];

    float denom = (float)NTOK;
    #pragma unroll
    for (int m = 0; m < 12; m++) denom = fmaf(qn[m], ksum_s[m], denom);
    float tail = 1.0f / denom;

    float* ob = g_out + (size_t)(b*CH + h*DH)*HW + pix;
    #pragma unroll
    for (int c2 = 0; c2 < 12; c2++) {
        float v = vsum_s[c2];
        #pragma unroll
        for (int m = 0; m < 12; m++) v = fmaf(qn[m], kv_s[m*12 + c2], v);
        ob[(size_t)c2*HW] = v * tail;
    }
}

// ---------------------------------------------------------------------------
// K_bnstats: per-channel sum / sumsq over g_y. grid (96, 8).
// ---------------------------------------------------------------------------
__global__ void __launch_bounds__(256)
k_bnstats()
{
    __shared__ float s_s[8], s_q[8];
    const int c = blockIdx.x, b = blockIdx.y;
    const int tid = threadIdx.x;

    const float4* p = reinterpret_cast<const float4*>(g_y + (size_t)(b*CH + c)*HW);
    float s = 0.f, q = 0.f;
    for (int i = tid; i < HW/4; i += 256) {
        float4 v = p[i];
        s += v.x + v.y + v.z + v.w;
        q += v.x*v.x + v.y*v.y + v.z*v.z + v.w*v.w;
    }
    #pragma unroll
    for (int d = 16; d > 0; d >>= 1) {
        s += __shfl_xor_sync(0xffffffffu, s, d);
        q += __shfl_xor_sync(0xffffffffu, q, d);
    }
    if ((tid & 31) == 0) { s_s[tid >> 5] = s; s_q[tid >> 5] = q; }
    __syncthreads();
    if (tid == 0) {
        float ts = 0.f, tq = 0.f;
        #pragma unroll
        for (int i = 0; i < 8; i++) { ts += s_s[i]; tq += s_q[i]; }
        atomicAdd(&g_sum[c], ts);
        atomicAdd(&g_sq[c],  tq);
    }
}

// ---------------------------------------------------------------------------
__global__ void k_bnprep(const float* __restrict__ gamma, const float* __restrict__ beta)
{
    int c = threadIdx.x;
    if (c < CH) {
        const float inv_n = 1.0f / (float)NPIX;
        float mean = g_sum[c] * inv_n;
        float var  = fmaf(-mean, mean, g_sq[c] * inv_n);
        float rstd = rsqrtf(var + BN_EPS);
        float sc = rstd * gamma[c];
        g_scale[c] = sc;
        g_shift[c] = fmaf(-mean, sc, beta[c]);
    }
}

__global__ void __launch_bounds__(256)
k_bnapply(float* __restrict__ out)
{
    int i = blockIdx.x * 256 + threadIdx.x;
    int c = (i >> 14) % CH;
    float sc = g_scale[c], sh = g_shift[c];
    float4 v = reinterpret_cast<const float4*>(g_y)[i];
    v.x = fmaf(v.x, sc, sh);
    v.y = fmaf(v.y, sc, sh);
    v.z = fmaf(v.z, sc, sh);
    v.w = fmaf(v.w, sc, sh);
    reinterpret_cast<float4*>(out)[i] = v;
}

// ---------------------------------------------------------------------------
extern "C" void kernel_launch(void* const* d_in, const int* in_sizes, int n_in,
                              void* d_out, int out_size)
{
    const float* x      = (const float*)d_in[0];
    const float* w_qkv  = (const float*)d_in[1];
    const float* w_proj = (const float*)d_in[2];
    const float* gamma  = (const float*)d_in[3];
    const float* beta   = (const float*)d_in[4];

    const int smem_attn = ATTN_SMEM_FLOATS * (int)sizeof(float);
    cudaFuncSetAttribute(k_gemm, cudaFuncAttributeMaxDynamicSharedMemorySize, SM_GEMM_TOTAL);
    cudaFuncSetAttribute(k_attn, cudaFuncAttributeMaxDynamicSharedMemorySize, smem_attn);

    float* gqkv;  cudaGetSymbolAddress((void**)&gqkv, g_qkv);
    float* gout;  cudaGetSymbolAddress((void**)&gout, g_out);
    float* gy;    cudaGetSymbolAddress((void**)&gy,   g_y);

    k_zero<<<1, 128>>>();
    k_wsplit<<<144, 256>>>(w_qkv, w_proj);
    k_gemm<<<4096, 256, SM_GEMM_TOTAL>>>(x, gqkv, 3, 0, 1);
    k_attn<<<dim3(NWIN, NH), 256, smem_attn>>>();
    k_gemm<<<4096, 256, SM_GEMM_TOTAL>>>(gout, gy, 1, 3, 0);
    k_bnstats<<<dim3(CH, BATCH), 256>>>();
    k_bnprep<<<1, 128>>>(gamma, beta);
    k_bnapply<<<TOTAL/4/256, 256>>>((float*)d_out);
}